// round 4
// baseline (speedup 1.0000x reference)
#include <cuda_runtime.h>
#include <cuda_bf16.h>
#include <mma.h>
#include <math.h>

using namespace nvcuda;

// Problem constants
#define BT   32768
#define DIN  768
#define DH   384
#define DH2  192
#define DOUT 256
#define NE   5
#define DELTA 0.35f   // z-gap ambiguity threshold (z err ~6e-3 RMS -> 58x margin)

// GEMM tile config
#define BM 128
#define BN 128
#define BKK 16
#define LDS_PAD 20
#define ABUF 2560
#define BBUF 2560

// ---------------- scratch (device globals) ----------------
__device__ float g_bufA[(size_t)BT * DH];
__device__ float g_bufB[(size_t)BT * DH];
__device__ float g_Y[(size_t)BT * DOUT];
__device__ float g_wc[(size_t)NE * DOUT * DOUT];
__device__ float g_bc[NE * DOUT];
__device__ int   g_eidx[BT];
__device__ int   g_perm[BT];
__device__ int   g_rowexp[BT];
__device__ int   g_cnt[NE];
__device__ int   g_off[NE + 1];
__device__ int   g_cur[NE];
__device__ int   g_flag[BT];
__device__ int   g_nflag;

__device__ __forceinline__ float tf32r(float x) { return wmma::__float_to_tf32(x); }
__device__ __forceinline__ float4 tf32r4(float4 v) {
    v.x = tf32r(v.x); v.y = tf32r(v.y); v.z = tf32r(v.z); v.w = tf32r(v.w);
    return v;
}

// ================= tensor-core GEMM (plain tf32): C = A.W^T + bias ==============
// seg != nullptr => expert-segmented (blockIdx.z = expert); gather maps rows.
__global__ void __launch_bounds__(256, 2)
gemm_tc(const float* __restrict__ A, const int* __restrict__ gather,
        const float* __restrict__ W, const float* __restrict__ bias,
        float* __restrict__ C, int N, int K,
        const int* __restrict__ seg, long wstride, int bstride, int Mtot)
{
    __shared__ __align__(16) float sm[ABUF * 2 + BBUF * 2];
    float* SA = sm;
    float* SB = sm + ABUF * 2;

    int e = 0, rowbase = 0, segM = Mtot;
    if (seg) { e = blockIdx.z; rowbase = seg[e]; segM = seg[e + 1] - rowbase; }
    int mt = blockIdx.x * BM;
    if (mt >= segM) return;

    const float* Wp = W + (long)e * wstride;
    const float* bp = bias + (long)e * bstride;
    int n0 = blockIdx.y * BN;

    int tid = threadIdx.x;
    int wid = tid >> 5;
    int wm  = wid >> 1;
    int wn  = wid & 1;

    int idx0 = tid, idx1 = tid + 256;
    int rA0 = idx0 >> 2, cA0 = (idx0 & 3) * 4;
    int rA1 = idx1 >> 2, cA1 = (idx1 & 3) * 4;
    int mr0 = mt + rA0; if (mr0 > segM - 1) mr0 = segM - 1;
    int mr1 = mt + rA1; if (mr1 > segM - 1) mr1 = segM - 1;
    int ar0 = gather ? gather[rowbase + mr0] : rowbase + mr0;
    int ar1 = gather ? gather[rowbase + mr1] : rowbase + mr1;
    const float* ap0 = A + (size_t)ar0 * K + cA0;
    const float* ap1 = A + (size_t)ar1 * K + cA1;
    int sA0 = rA0 * LDS_PAD + cA0;
    int sA1 = rA1 * LDS_PAD + cA1;

    int nr0 = n0 + rA0; if (nr0 > N - 1) nr0 = N - 1;
    int nr1 = n0 + rA1; if (nr1 > N - 1) nr1 = N - 1;
    const float* bpt0 = Wp + (size_t)nr0 * K + cA0;
    const float* bpt1 = Wp + (size_t)nr1 * K + cA1;

    wmma::fragment<wmma::accumulator, 16, 16, 8, float> acc[2][4];
    #pragma unroll
    for (int mi = 0; mi < 2; mi++)
        #pragma unroll
        for (int ni = 0; ni < 4; ni++) wmma::fill_fragment(acc[mi][ni], 0.f);

    float4 ra0 = *(const float4*)(ap0);
    float4 ra1 = *(const float4*)(ap1);
    float4 rb0 = *(const float4*)(bpt0);
    float4 rb1 = *(const float4*)(bpt1);

    int nk = K / BKK;
    *(float4*)(SA + sA0) = tf32r4(ra0); *(float4*)(SA + sA1) = tf32r4(ra1);
    *(float4*)(SB + sA0) = tf32r4(rb0); *(float4*)(SB + sA1) = tf32r4(rb1);
    __syncthreads();

    for (int kb = 0; kb < nk; kb++) {
        int buf = kb & 1;
        if (kb + 1 < nk) {
            int k = (kb + 1) * BKK;
            ra0 = *(const float4*)(ap0 + k);
            ra1 = *(const float4*)(ap1 + k);
            rb0 = *(const float4*)(bpt0 + k);
            rb1 = *(const float4*)(bpt1 + k);
        }
        const float* sa = SA + buf * ABUF;
        const float* sb = SB + buf * BBUF;
        #pragma unroll
        for (int ks = 0; ks < 2; ks++) {
            wmma::fragment<wmma::matrix_a, 16, 16, 8, wmma::precision::tf32, wmma::row_major> a[2];
            wmma::fragment<wmma::matrix_b, 16, 16, 8, wmma::precision::tf32, wmma::col_major> b[4];
            #pragma unroll
            for (int mi = 0; mi < 2; mi++)
                wmma::load_matrix_sync(a[mi], sa + (wm * 32 + mi * 16) * LDS_PAD + ks * 8, LDS_PAD);
            #pragma unroll
            for (int ni = 0; ni < 4; ni++)
                wmma::load_matrix_sync(b[ni], sb + (wn * 64 + ni * 16) * LDS_PAD + ks * 8, LDS_PAD);
            #pragma unroll
            for (int mi = 0; mi < 2; mi++)
                #pragma unroll
                for (int ni = 0; ni < 4; ni++)
                    wmma::mma_sync(acc[mi][ni], a[mi], b[ni], acc[mi][ni]);
        }
        if (kb + 1 < nk) {
            int nb = buf ^ 1;
            *(float4*)(SA + nb * ABUF + sA0) = tf32r4(ra0);
            *(float4*)(SA + nb * ABUF + sA1) = tf32r4(ra1);
            *(float4*)(SB + nb * BBUF + sA0) = tf32r4(rb0);
            *(float4*)(SB + nb * BBUF + sA1) = tf32r4(rb1);
            __syncthreads();
        }
    }

    __syncthreads();
    float* stage = sm;
    const int SLD = 132;
    #pragma unroll
    for (int r = 0; r < 2; r++) {
        if ((wm >> 1) == r) {
            #pragma unroll
            for (int mi = 0; mi < 2; mi++)
                #pragma unroll
                for (int ni = 0; ni < 4; ni++)
                    wmma::store_matrix_sync(stage + ((wm & 1) * 32 + mi * 16) * SLD + wn * 64 + ni * 16,
                                            acc[mi][ni], SLD, wmma::mem_row_major);
        }
        __syncthreads();
        #pragma unroll
        for (int it = 0; it < 8; it++) {
            int fidx = tid + it * 256;
            int lrow = fidx >> 5;
            int c4 = (fidx & 31) * 4;
            int m = mt + r * 64 + lrow;
            int n = n0 + c4;
            if (m < segM && n < N) {
                float4 v = *(float4*)(stage + lrow * SLD + c4);
                float4 bv = *(const float4*)(bp + n);
                v.x += bv.x; v.y += bv.y; v.z += bv.z; v.w += bv.w;
                *(float4*)(C + (size_t)(rowbase + m) * N + n) = v;
            }
        }
        __syncthreads();
    }
}

// ---------------- fuse wo @ wv ----------------------------------------------------
__global__ void fuse_wo_wv(const float* __restrict__ wqkv, const float* __restrict__ bqkv,
                           const float* __restrict__ wo, const float* __restrict__ bo,
                           float* __restrict__ wc, float* __restrict__ bc)
{
    int e = blockIdx.z, n = blockIdx.y, k = threadIdx.x;
    const float* woR = wo + ((size_t)e * DOUT + n) * DOUT;
    const float* wv  = wqkv + (size_t)e * 3 * DOUT * DOUT + 2 * DOUT * DOUT;
    const float* bv  = bqkv + (size_t)e * 3 * DOUT + 2 * DOUT;
    float s = 0.f;
    for (int j = 0; j < DOUT; j++) s = fmaf(woR[j], wv[(size_t)j * DOUT + k], s);
    wc[((size_t)e * DOUT + n) * DOUT + k] = s;
    if (k == 0) {
        float sb = bo[e * DOUT + n];
        for (int j = 0; j < DOUT; j++) sb = fmaf(woR[j], bv[j], sb);
        bc[e * DOUT + n] = sb;
    }
}

// ---------------- row LayerNorm (+optional ReLU), warp per row -------------------
__global__ void ln_rows(const float* __restrict__ in, float* __restrict__ out, int Ncols,
                        const float* __restrict__ g, const float* __restrict__ b,
                        int gstride, int doRelu, const int* __restrict__ rowexp, int M)
{
    int row = blockIdx.x * 8 + (threadIdx.x >> 5);
    if (row >= M) return;
    int lane = threadIdx.x & 31;
    int e = rowexp ? rowexp[row] : 0;
    const float* ip = in + (size_t)row * Ncols;
    int nw = Ncols >> 5;

    float v[12];
    float s = 0.f;
    for (int i = 0; i < nw; i++) { v[i] = ip[lane + i * 32]; s += v[i]; }
    #pragma unroll
    for (int o = 16; o; o >>= 1) s += __shfl_xor_sync(0xffffffffu, s, o);
    float mu = s / (float)Ncols;

    float sq = 0.f;
    for (int i = 0; i < nw; i++) { float d = v[i] - mu; sq += d * d; }
    #pragma unroll
    for (int o = 16; o; o >>= 1) sq += __shfl_xor_sync(0xffffffffu, sq, o);
    float inv = 1.0f / sqrtf(sq / (float)Ncols + 1e-5f);

    const float* gp = g + (long)e * gstride;
    const float* bp = b + (long)e * gstride;
    float* op = out + (size_t)row * Ncols;
    for (int i = 0; i < nw; i++) {
        int c = lane + i * 32;
        float o2 = (v[i] - mu) * inv * gp[c] + bp[c];
        if (doRelu) o2 = fmaxf(o2, 0.f);
        op[c] = o2;
    }
}

// ---------------- router head: provisional (tf32-based) + ambiguity flagging -----
__global__ void routing_kernel(const float* __restrict__ h2, const float* __restrict__ rw3,
                               const float* __restrict__ rb3, const float* __restrict__ gumbel,
                               float* __restrict__ outRW, float* __restrict__ outIdx)
{
    int tok = blockIdx.x * 8 + (threadIdx.x >> 5);
    if (tok >= BT) return;
    int lane = threadIdx.x & 31;
    const float* h = h2 + (size_t)tok * DH2;

    float acc[NE];
    #pragma unroll
    for (int j = 0; j < NE; j++) acc[j] = 0.f;
    #pragma unroll
    for (int i = 0; i < DH2 / 32; i++) {
        int k = lane + i * 32;
        float hv = h[k];
        #pragma unroll
        for (int j = 0; j < NE; j++)
            acc[j] = fmaf(hv, rw3[j * DH2 + k], acc[j]);
    }
    #pragma unroll
    for (int j = 0; j < NE; j++)
        #pragma unroll
        for (int o = 16; o; o >>= 1)
            acc[j] += __shfl_xor_sync(0xffffffffu, acc[j], o);

    if (lane == 0) {
        float z[NE];
        float best = -1e30f, second = -1e30f; int bi = 0;
        #pragma unroll
        for (int j = 0; j < NE; j++) {
            float lg = acc[j] + rb3[j];
            z[j] = (lg + gumbel[(size_t)tok * NE + j]) / 0.07f;
            if (z[j] > best) { second = best; best = z[j]; bi = j; }
            else if (z[j] > second) second = z[j];
        }
        float ex[NE], sum = 0.f;
        #pragma unroll
        for (int j = 0; j < NE; j++) { ex[j] = expf(z[j] - best); sum += ex[j]; }
        #pragma unroll
        for (int j = 0; j < NE; j++) {
            float ys = ex[j] / sum;
            float hard = (j == bi) ? 1.f : 0.f;
            outRW[(size_t)tok * NE + j] = (hard + ys) - ys;
        }
        outIdx[tok] = (float)bi;
        g_eidx[tok] = bi;
        atomicAdd(&g_cnt[bi], 1);
        if (best - second < DELTA) {
            int p = atomicAdd(&g_nflag, 1);
            g_flag[p] = tok;
        }
    }
}

// ---------------- exact fp32 recompute for ambiguous tokens ----------------------
__global__ void __launch_bounds__(192)
recheck_kernel(const float* __restrict__ x, const float* __restrict__ gumbel,
               const float* __restrict__ rw1, const float* __restrict__ rb1,
               const float* __restrict__ rg1, const float* __restrict__ rbe1,
               const float* __restrict__ rw2, const float* __restrict__ rb2,
               const float* __restrict__ rg2, const float* __restrict__ rbe2,
               const float* __restrict__ rw3, const float* __restrict__ rb3,
               float* __restrict__ outRW, float* __restrict__ outIdx)
{
    __shared__ float xs[DIN];
    __shared__ float h1[DH];
    __shared__ float h2s[DH2];
    __shared__ float red[8];
    __shared__ float lg[NE];
    int tid = threadIdx.x;
    int lane = tid & 31, wid = tid >> 5;
    int nf = g_nflag;

    for (int fi = blockIdx.x; fi < nf; fi += gridDim.x) {
        int tok = g_flag[fi];
        for (int k = tid; k < DIN; k += 192) xs[k] = x[(size_t)tok * DIN + k];
        __syncthreads();

        // layer 1: 384 x dot(768), fp32
        for (int j = tid; j < DH; j += 192) {
            const float* w = rw1 + (size_t)j * DIN;
            float s = rb1[j];
            for (int k = 0; k < DIN; k++) s = fmaf(xs[k], w[k], s);
            h1[j] = s;
        }
        __syncthreads();
        // LN(384) + relu
        {
            float s = 0.f;
            for (int j = tid; j < DH; j += 192) s += h1[j];
            #pragma unroll
            for (int o = 16; o; o >>= 1) s += __shfl_xor_sync(0xffffffffu, s, o);
            if (lane == 0) red[wid] = s;
            __syncthreads();
            if (tid == 0) { float t = 0; for (int w = 0; w < 6; w++) t += red[w]; red[6] = t / DH; }
            __syncthreads();
            float mu = red[6];
            float sq = 0.f;
            for (int j = tid; j < DH; j += 192) { float d = h1[j] - mu; sq += d * d; }
            #pragma unroll
            for (int o = 16; o; o >>= 1) sq += __shfl_xor_sync(0xffffffffu, sq, o);
            if (lane == 0) red[wid] = sq;
            __syncthreads();
            if (tid == 0) { float t = 0; for (int w = 0; w < 6; w++) t += red[w]; red[7] = 1.0f / sqrtf(t / DH + 1e-5f); }
            __syncthreads();
            float inv = red[7];
            for (int j = tid; j < DH; j += 192)
                h1[j] = fmaxf((h1[j] - mu) * inv * rg1[j] + rbe1[j], 0.f);
            __syncthreads();
        }
        // layer 2: 192 x dot(384)
        for (int j = tid; j < DH2; j += 192) {
            const float* w = rw2 + (size_t)j * DH;
            float s = rb2[j];
            for (int k = 0; k < DH; k++) s = fmaf(h1[k], w[k], s);
            h2s[j] = s;
        }
        __syncthreads();
        // LN(192) + relu
        {
            float s = (tid < DH2) ? h2s[tid] : 0.f;
            #pragma unroll
            for (int o = 16; o; o >>= 1) s += __shfl_xor_sync(0xffffffffu, s, o);
            if (lane == 0) red[wid] = s;
            __syncthreads();
            if (tid == 0) { float t = 0; for (int w = 0; w < 6; w++) t += red[w]; red[6] = t / DH2; }
            __syncthreads();
            float mu = red[6];
            float d = (tid < DH2) ? (h2s[tid] - mu) : 0.f;
            float sq = d * d;
            #pragma unroll
            for (int o = 16; o; o >>= 1) sq += __shfl_xor_sync(0xffffffffu, sq, o);
            if (lane == 0) red[wid] = sq;
            __syncthreads();
            if (tid == 0) { float t = 0; for (int w = 0; w < 6; w++) t += red[w]; red[7] = 1.0f / sqrtf(t / DH2 + 1e-5f); }
            __syncthreads();
            if (tid < DH2)
                h2s[tid] = fmaxf((h2s[tid] - mu) * red[7] * rg2[tid] + rbe2[tid], 0.f);
            __syncthreads();
        }
        // logits: warps 0..4 each compute one dot(192)
        if (wid < NE) {
            float s = 0.f;
            for (int k = lane; k < DH2; k += 32)
                s = fmaf(h2s[k], rw3[wid * DH2 + k], s);
            #pragma unroll
            for (int o = 16; o; o >>= 1) s += __shfl_xor_sync(0xffffffffu, s, o);
            if (lane == 0) lg[wid] = s + rb3[wid];
        }
        __syncthreads();
        if (tid == 0) {
            float z[NE];
            float best = -1e30f; int bi = 0;
            #pragma unroll
            for (int j = 0; j < NE; j++) {
                z[j] = (lg[j] + gumbel[(size_t)tok * NE + j]) / 0.07f;
                if (z[j] > best) { best = z[j]; bi = j; }
            }
            float ex[NE], sum = 0.f;
            #pragma unroll
            for (int j = 0; j < NE; j++) { ex[j] = expf(z[j] - best); sum += ex[j]; }
            #pragma unroll
            for (int j = 0; j < NE; j++) {
                float ys = ex[j] / sum;
                float hard = (j == bi) ? 1.f : 0.f;
                outRW[(size_t)tok * NE + j] = (hard + ys) - ys;
            }
            outIdx[tok] = (float)bi;
            int old = g_eidx[tok];
            if (bi != old) {
                atomicSub(&g_cnt[old], 1);
                atomicAdd(&g_cnt[bi], 1);
                g_eidx[tok] = bi;
            }
        }
        __syncthreads();
    }
}

__global__ void scan_kernel()
{
    if (threadIdx.x == 0 && blockIdx.x == 0) {
        int o = 0;
        for (int e = 0; e < NE; e++) { g_off[e] = o; g_cur[e] = o; o += g_cnt[e]; }
        g_off[NE] = o;
    }
}

__global__ void fill_perm()
{
    int t = blockIdx.x * blockDim.x + threadIdx.x;
    if (t < BT) {
        int e = g_eidx[t];
        int p = atomicAdd(&g_cur[e], 1);
        g_perm[p]   = t;
        g_rowexp[p] = e;
    }
}

// ---------------- final: LN(Y + O) scattered back to token order ------------------
__global__ void final_kernel(const float* __restrict__ Y, const float* __restrict__ O,
                             const float* __restrict__ ng, const float* __restrict__ nb,
                             float* __restrict__ outMain)
{
    int r = blockIdx.x * 8 + (threadIdx.x >> 5);
    if (r >= BT) return;
    int lane = threadIdx.x & 31;
    int e = g_rowexp[r];
    int t = g_perm[r];

    float v[8];
    float s = 0.f;
    #pragma unroll
    for (int i = 0; i < 8; i++) {
        int c = lane + i * 32;
        v[i] = Y[(size_t)r * DOUT + c] + O[(size_t)r * DOUT + c];
        s += v[i];
    }
    #pragma unroll
    for (int o = 16; o; o >>= 1) s += __shfl_xor_sync(0xffffffffu, s, o);
    float mu = s / (float)DOUT;
    float sq = 0.f;
    #pragma unroll
    for (int i = 0; i < 8; i++) { float d = v[i] - mu; sq += d * d; }
    #pragma unroll
    for (int o = 16; o; o >>= 1) sq += __shfl_xor_sync(0xffffffffu, sq, o);
    float inv = 1.0f / sqrtf(sq / (float)DOUT + 1e-5f);

    const float* gp = ng + (long)e * DOUT;
    const float* bp = nb + (long)e * DOUT;
    float* op = outMain + (size_t)t * DOUT;
    #pragma unroll
    for (int i = 0; i < 8; i++) {
        int c = lane + i * 32;
        op[c] = (v[i] - mu) * inv * gp[c] + bp[c];
    }
}

// ---------------- launch ----------------------------------------------------------
extern "C" void kernel_launch(void* const* d_in, const int* in_sizes, int n_in,
                              void* d_out, int out_size)
{
    const float* x      = (const float*)d_in[0];
    const float* gumbel = (const float*)d_in[1];
    const float* rw1  = (const float*)d_in[2];
    const float* rb1  = (const float*)d_in[3];
    const float* rg1  = (const float*)d_in[4];
    const float* rbe1 = (const float*)d_in[5];
    const float* rw2  = (const float*)d_in[6];
    const float* rb2  = (const float*)d_in[7];
    const float* rg2  = (const float*)d_in[8];
    const float* rbe2 = (const float*)d_in[9];
    const float* rw3  = (const float*)d_in[10];
    const float* rb3  = (const float*)d_in[11];
    const float* ew1  = (const float*)d_in[12];
    const float* eb1  = (const float*)d_in[13];
    const float* eg1  = (const float*)d_in[14];
    const float* ebe1 = (const float*)d_in[15];
    const float* ew2  = (const float*)d_in[16];
    const float* eb2  = (const float*)d_in[17];
    const float* eg2  = (const float*)d_in[18];
    const float* ebe2 = (const float*)d_in[19];
    const float* ew3  = (const float*)d_in[20];
    const float* eb3  = (const float*)d_in[21];
    const float* eg3  = (const float*)d_in[22];
    const float* ebe3 = (const float*)d_in[23];
    const float* wqkv = (const float*)d_in[24];
    const float* bqkv = (const float*)d_in[25];
    const float* wo   = (const float*)d_in[26];
    const float* bo   = (const float*)d_in[27];
    const float* ng   = (const float*)d_in[28];
    const float* nb   = (const float*)d_in[29];

    float* outMain = (float*)d_out;
    float* outRW   = outMain + (size_t)BT * DOUT;
    float* outIdx  = outRW   + (size_t)BT * NE;

    float *bufA, *bufB, *Yb, *wc, *bc; int *off, *perm, *rowexp; void *cntp, *nflagp;
    cudaGetSymbolAddress((void**)&bufA,   g_bufA);
    cudaGetSymbolAddress((void**)&bufB,   g_bufB);
    cudaGetSymbolAddress((void**)&Yb,     g_Y);
    cudaGetSymbolAddress((void**)&wc,     g_wc);
    cudaGetSymbolAddress((void**)&bc,     g_bc);
    cudaGetSymbolAddress((void**)&off,    g_off);
    cudaGetSymbolAddress((void**)&perm,   g_perm);
    cudaGetSymbolAddress((void**)&rowexp, g_rowexp);
    cudaGetSymbolAddress(&cntp,           g_cnt);
    cudaGetSymbolAddress(&nflagp,         g_nflag);

    cudaMemsetAsync(cntp, 0, NE * sizeof(int));
    cudaMemsetAsync(nflagp, 0, sizeof(int));
    fuse_wo_wv<<<dim3(1, DOUT, NE), 256>>>(wqkv, bqkv, wo, bo, wc, bc);

    // ---- router (plain tf32 + exact recheck of ambiguous tokens) ----
    gemm_tc<<<dim3(BT / BM, DH / BN, 1), 256>>>(x, nullptr, rw1, rb1, bufA, DH, DIN,
                                                nullptr, 0, 0, BT);
    ln_rows<<<BT / 8, 256>>>(bufA, bufA, DH, rg1, rbe1, 0, 1, nullptr, BT);
    gemm_tc<<<dim3(BT / BM, (DH2 + BN - 1) / BN, 1), 256>>>(bufA, nullptr, rw2, rb2, bufB,
                                                            DH2, DH, nullptr, 0, 0, BT);
    ln_rows<<<BT / 8, 256>>>(bufB, bufB, DH2, rg2, rbe2, 0, 1, nullptr, BT);
    routing_kernel<<<BT / 8, 256>>>(bufB, rw3, rb3, gumbel, outRW, outIdx);
    recheck_kernel<<<256, 192>>>(x, gumbel, rw1, rb1, rg1, rbe1, rw2, rb2, rg2, rbe2,
                                 rw3, rb3, outRW, outIdx);
    scan_kernel<<<1, 32>>>();
    fill_perm<<<BT / 256, 256>>>();

    // ---- experts (compacted; plain tf32) ----
    gemm_tc<<<dim3(BT / BM, DH / BN, NE), 256>>>(x, perm, ew1, eb1, bufA, DH, DIN,
                                                 off, (long)DH * DIN, DH, BT);
    ln_rows<<<BT / 8, 256>>>(bufA, bufA, DH, eg1, ebe1, DH, 1, rowexp, BT);

    gemm_tc<<<dim3(BT / BM, DH / BN, NE), 256>>>(bufA, nullptr, ew2, eb2, bufB, DH, DH,
                                                 off, (long)DH * DH, DH, BT);
    ln_rows<<<BT / 8, 256>>>(bufB, bufB, DH, eg2, ebe2, DH, 1, rowexp, BT);

    gemm_tc<<<dim3(BT / BM, DOUT / BN, NE), 256>>>(bufB, nullptr, ew3, eb3, Yb, DOUT, DH,
                                                   off, (long)DOUT * DH, DOUT, BT);
    ln_rows<<<BT / 8, 256>>>(Yb, Yb, DOUT, eg3, ebe3, DOUT, 0, rowexp, BT);

    // attention over length-1 seq == V; V-proj and O-proj fused into wc/bc
    gemm_tc<<<dim3(BT / BM, DOUT / BN, NE), 256>>>(Yb, nullptr, wc, bc, bufA, DOUT, DOUT,
                                                   off, (long)DOUT * DOUT, DOUT, BT);

    final_kernel<<<BT / 8, 256>>>(Yb, bufA, ng, nb, outMain);
}

// round 5
// speedup vs baseline: 1.5300x; 1.5300x over previous
#include <cuda_runtime.h>
#include <cuda_bf16.h>
#include <mma.h>
#include <math.h>

using namespace nvcuda;

// Problem constants
#define BT   32768
#define DIN  768
#define DH   384
#define DH2  192
#define DOUT 256
#define NE   5
#define DELTA 0.35f   // z-gap ambiguity threshold

// GEMM tile config
#define BM 128
#define BN 128
#define BKK 16
#define LDS_PAD 20
#define ABUF 2560
#define BBUF 2560

// ---------------- scratch (device globals) ----------------
__device__ float g_bufA[(size_t)BT * DH];
__device__ float g_bufB[(size_t)BT * DH];
__device__ float g_Y[(size_t)BT * DOUT];
__device__ float g_fA[(size_t)BT * DH];    // flagged-token exact h1
__device__ float g_fB[(size_t)BT * DH2];   // flagged-token exact h2
__device__ float g_wc[(size_t)NE * DOUT * DOUT];
__device__ float g_bc[NE * DOUT];
__device__ int   g_eidx[BT];
__device__ int   g_perm[BT];
__device__ int   g_rowexp[BT];
__device__ int   g_cnt[NE];
__device__ int   g_off[NE + 1];
__device__ int   g_cur[NE];
__device__ int   g_flag[BT];
__device__ int   g_nflag;
__device__ int   g_nseg[2];

__device__ __forceinline__ float tf32r(float x) { return wmma::__float_to_tf32(x); }
__device__ __forceinline__ float4 tf32r4(float4 v) {
    v.x = tf32r(v.x); v.y = tf32r(v.y); v.z = tf32r(v.z); v.w = tf32r(v.w);
    return v;
}

// ============ tensor-core GEMM: C = A.W^T + bias ============
// SPLIT=1: 3-term split-tf32 (~2^-24, exact-grade) — flagged recheck path.
// SPLIT=0: plain tf32 — bulk router + experts.
// seg != nullptr => segmented (blockIdx.z selects segment); gather maps rows of A.
template<int SPLIT>
__global__ void __launch_bounds__(256, SPLIT ? 1 : 2)
gemm_tc(const float* __restrict__ A, const int* __restrict__ gather,
        const float* __restrict__ W, const float* __restrict__ bias,
        float* __restrict__ C, int N, int K,
        const int* __restrict__ seg, long wstride, int bstride, int Mtot)
{
    __shared__ __align__(16) float sm[ABUF * 2 + BBUF * 2];
    float* SA = sm;
    float* SB = sm + ABUF * 2;

    int e = 0, rowbase = 0, segM = Mtot;
    if (seg) { e = blockIdx.z; rowbase = seg[e]; segM = seg[e + 1] - rowbase; }
    int mt = blockIdx.x * BM;
    if (mt >= segM) return;

    const float* Wp = W + (long)e * wstride;
    const float* bp = bias + (long)e * bstride;
    int n0 = blockIdx.y * BN;

    int tid = threadIdx.x;
    int wid = tid >> 5;
    int wm  = wid >> 1;
    int wn  = wid & 1;

    int idx0 = tid, idx1 = tid + 256;
    int rA0 = idx0 >> 2, cA0 = (idx0 & 3) * 4;
    int rA1 = idx1 >> 2, cA1 = (idx1 & 3) * 4;
    int mr0 = mt + rA0; if (mr0 > segM - 1) mr0 = segM - 1;
    int mr1 = mt + rA1; if (mr1 > segM - 1) mr1 = segM - 1;
    int ar0 = gather ? gather[rowbase + mr0] : rowbase + mr0;
    int ar1 = gather ? gather[rowbase + mr1] : rowbase + mr1;
    const float* ap0 = A + (size_t)ar0 * K + cA0;
    const float* ap1 = A + (size_t)ar1 * K + cA1;
    int sA0 = rA0 * LDS_PAD + cA0;
    int sA1 = rA1 * LDS_PAD + cA1;

    int nr0 = n0 + rA0; if (nr0 > N - 1) nr0 = N - 1;
    int nr1 = n0 + rA1; if (nr1 > N - 1) nr1 = N - 1;
    const float* bpt0 = Wp + (size_t)nr0 * K + cA0;
    const float* bpt1 = Wp + (size_t)nr1 * K + cA1;

    wmma::fragment<wmma::accumulator, 16, 16, 8, float> acc[2][4];
    #pragma unroll
    for (int mi = 0; mi < 2; mi++)
        #pragma unroll
        for (int ni = 0; ni < 4; ni++) wmma::fill_fragment(acc[mi][ni], 0.f);

    float4 ra0 = *(const float4*)(ap0);
    float4 ra1 = *(const float4*)(ap1);
    float4 rb0 = *(const float4*)(bpt0);
    float4 rb1 = *(const float4*)(bpt1);

    int nk = K / BKK;
    {
        float4 a0 = SPLIT ? ra0 : tf32r4(ra0);
        float4 a1 = SPLIT ? ra1 : tf32r4(ra1);
        float4 b0 = SPLIT ? rb0 : tf32r4(rb0);
        float4 b1 = SPLIT ? rb1 : tf32r4(rb1);
        *(float4*)(SA + sA0) = a0; *(float4*)(SA + sA1) = a1;
        *(float4*)(SB + sA0) = b0; *(float4*)(SB + sA1) = b1;
    }
    __syncthreads();

    for (int kb = 0; kb < nk; kb++) {
        int buf = kb & 1;
        if (kb + 1 < nk) {
            int k = (kb + 1) * BKK;
            ra0 = *(const float4*)(ap0 + k);
            ra1 = *(const float4*)(ap1 + k);
            rb0 = *(const float4*)(bpt0 + k);
            rb1 = *(const float4*)(bpt1 + k);
        }
        const float* sa = SA + buf * ABUF;
        const float* sb = SB + buf * BBUF;
        #pragma unroll
        for (int ks = 0; ks < 2; ks++) {
            wmma::fragment<wmma::matrix_a, 16, 16, 8, wmma::precision::tf32, wmma::row_major> a[2];
            wmma::fragment<wmma::matrix_b, 16, 16, 8, wmma::precision::tf32, wmma::col_major> b[4];
            #pragma unroll
            for (int mi = 0; mi < 2; mi++)
                wmma::load_matrix_sync(a[mi], sa + (wm * 32 + mi * 16) * LDS_PAD + ks * 8, LDS_PAD);
            #pragma unroll
            for (int ni = 0; ni < 4; ni++)
                wmma::load_matrix_sync(b[ni], sb + (wn * 64 + ni * 16) * LDS_PAD + ks * 8, LDS_PAD);

            if (SPLIT) {
                wmma::fragment<wmma::matrix_a, 16, 16, 8, wmma::precision::tf32, wmma::row_major> ah[2];
                wmma::fragment<wmma::matrix_b, 16, 16, 8, wmma::precision::tf32, wmma::col_major> bh[4];
                #pragma unroll
                for (int mi = 0; mi < 2; mi++)
                    #pragma unroll
                    for (int i = 0; i < a[mi].num_elements; i++) {
                        float h = tf32r(a[mi].x[i]);
                        ah[mi].x[i] = h;
                        a[mi].x[i] = tf32r(a[mi].x[i] - h);
                    }
                #pragma unroll
                for (int ni = 0; ni < 4; ni++)
                    #pragma unroll
                    for (int i = 0; i < b[ni].num_elements; i++) {
                        float h = tf32r(b[ni].x[i]);
                        bh[ni].x[i] = h;
                        b[ni].x[i] = tf32r(b[ni].x[i] - h);
                    }
                #pragma unroll
                for (int mi = 0; mi < 2; mi++)
                    #pragma unroll
                    for (int ni = 0; ni < 4; ni++) {
                        wmma::mma_sync(acc[mi][ni], ah[mi], bh[ni], acc[mi][ni]);
                        wmma::mma_sync(acc[mi][ni], ah[mi], b[ni],  acc[mi][ni]);
                        wmma::mma_sync(acc[mi][ni], a[mi],  bh[ni], acc[mi][ni]);
                    }
            } else {
                #pragma unroll
                for (int mi = 0; mi < 2; mi++)
                    #pragma unroll
                    for (int ni = 0; ni < 4; ni++)
                        wmma::mma_sync(acc[mi][ni], a[mi], b[ni], acc[mi][ni]);
            }
        }
        if (kb + 1 < nk) {
            int nb = buf ^ 1;
            float4 a0 = SPLIT ? ra0 : tf32r4(ra0);
            float4 a1 = SPLIT ? ra1 : tf32r4(ra1);
            float4 b0 = SPLIT ? rb0 : tf32r4(rb0);
            float4 b1 = SPLIT ? rb1 : tf32r4(rb1);
            *(float4*)(SA + nb * ABUF + sA0) = a0;
            *(float4*)(SA + nb * ABUF + sA1) = a1;
            *(float4*)(SB + nb * BBUF + sA0) = b0;
            *(float4*)(SB + nb * BBUF + sA1) = b1;
            __syncthreads();
        }
    }

    __syncthreads();
    float* stage = sm;
    const int SLD = 132;
    #pragma unroll
    for (int r = 0; r < 2; r++) {
        if ((wm >> 1) == r) {
            #pragma unroll
            for (int mi = 0; mi < 2; mi++)
                #pragma unroll
                for (int ni = 0; ni < 4; ni++)
                    wmma::store_matrix_sync(stage + ((wm & 1) * 32 + mi * 16) * SLD + wn * 64 + ni * 16,
                                            acc[mi][ni], SLD, wmma::mem_row_major);
        }
        __syncthreads();
        #pragma unroll
        for (int it = 0; it < 8; it++) {
            int fidx = tid + it * 256;
            int lrow = fidx >> 5;
            int c4 = (fidx & 31) * 4;
            int m = mt + r * 64 + lrow;
            int n = n0 + c4;
            if (m < segM && n < N) {
                float4 v = *(float4*)(stage + lrow * SLD + c4);
                float4 bv = *(const float4*)(bp + n);
                v.x += bv.x; v.y += bv.y; v.z += bv.z; v.w += bv.w;
                *(float4*)(C + (size_t)(rowbase + m) * N + n) = v;
            }
        }
        __syncthreads();
    }
}

// ---------------- fuse wo @ wv ----------------------------------------------------
__global__ void fuse_wo_wv(const float* __restrict__ wqkv, const float* __restrict__ bqkv,
                           const float* __restrict__ wo, const float* __restrict__ bo,
                           float* __restrict__ wc, float* __restrict__ bc)
{
    int e = blockIdx.z, n = blockIdx.y, k = threadIdx.x;
    const float* woR = wo + ((size_t)e * DOUT + n) * DOUT;
    const float* wv  = wqkv + (size_t)e * 3 * DOUT * DOUT + 2 * DOUT * DOUT;
    const float* bv  = bqkv + (size_t)e * 3 * DOUT + 2 * DOUT;
    float s = 0.f;
    for (int j = 0; j < DOUT; j++) s = fmaf(woR[j], wv[(size_t)j * DOUT + k], s);
    wc[((size_t)e * DOUT + n) * DOUT + k] = s;
    if (k == 0) {
        float sb = bo[e * DOUT + n];
        for (int j = 0; j < DOUT; j++) sb = fmaf(woR[j], bv[j], sb);
        bc[e * DOUT + n] = sb;
    }
}

// ---------------- row LayerNorm (+optional ReLU), warp per row -------------------
// Mdev != nullptr => row count read from device (flagged path).
__global__ void ln_rows(const float* __restrict__ in, float* __restrict__ out, int Ncols,
                        const float* __restrict__ g, const float* __restrict__ b,
                        int gstride, int doRelu, const int* __restrict__ rowexp, int M,
                        const int* __restrict__ Mdev)
{
    int row = blockIdx.x * 8 + (threadIdx.x >> 5);
    int Mr = Mdev ? *Mdev : M;
    if (row >= Mr) return;
    int lane = threadIdx.x & 31;
    int e = rowexp ? rowexp[row] : 0;
    const float* ip = in + (size_t)row * Ncols;
    int nw = Ncols >> 5;

    float v[12];
    float s = 0.f;
    for (int i = 0; i < nw; i++) { v[i] = ip[lane + i * 32]; s += v[i]; }
    #pragma unroll
    for (int o = 16; o; o >>= 1) s += __shfl_xor_sync(0xffffffffu, s, o);
    float mu = s / (float)Ncols;

    float sq = 0.f;
    for (int i = 0; i < nw; i++) { float d = v[i] - mu; sq += d * d; }
    #pragma unroll
    for (int o = 16; o; o >>= 1) sq += __shfl_xor_sync(0xffffffffu, sq, o);
    float inv = 1.0f / sqrtf(sq / (float)Ncols + 1e-5f);

    const float* gp = g + (long)e * gstride;
    const float* bp = b + (long)e * gstride;
    float* op = out + (size_t)row * Ncols;
    for (int i = 0; i < nw; i++) {
        int c = lane + i * 32;
        float o2 = (v[i] - mu) * inv * gp[c] + bp[c];
        if (doRelu) o2 = fmaxf(o2, 0.f);
        op[c] = o2;
    }
}

// ---------------- router head: provisional + ambiguity flagging -------------------
__global__ void routing_kernel(const float* __restrict__ h2, const float* __restrict__ rw3,
                               const float* __restrict__ rb3, const float* __restrict__ gumbel,
                               float* __restrict__ outRW, float* __restrict__ outIdx)
{
    int tok = blockIdx.x * 8 + (threadIdx.x >> 5);
    if (tok >= BT) return;
    int lane = threadIdx.x & 31;
    const float* h = h2 + (size_t)tok * DH2;

    float acc[NE];
    #pragma unroll
    for (int j = 0; j < NE; j++) acc[j] = 0.f;
    #pragma unroll
    for (int i = 0; i < DH2 / 32; i++) {
        int k = lane + i * 32;
        float hv = h[k];
        #pragma unroll
        for (int j = 0; j < NE; j++)
            acc[j] = fmaf(hv, rw3[j * DH2 + k], acc[j]);
    }
    #pragma unroll
    for (int j = 0; j < NE; j++)
        #pragma unroll
        for (int o = 16; o; o >>= 1)
            acc[j] += __shfl_xor_sync(0xffffffffu, acc[j], o);

    if (lane == 0) {
        float z[NE];
        float best = -1e30f, second = -1e30f; int bi = 0;
        #pragma unroll
        for (int j = 0; j < NE; j++) {
            float lg = acc[j] + rb3[j];
            z[j] = (lg + gumbel[(size_t)tok * NE + j]) / 0.07f;
            if (z[j] > best) { second = best; best = z[j]; bi = j; }
            else if (z[j] > second) second = z[j];
        }
        float ex[NE], sum = 0.f;
        #pragma unroll
        for (int j = 0; j < NE; j++) { ex[j] = expf(z[j] - best); sum += ex[j]; }
        #pragma unroll
        for (int j = 0; j < NE; j++) {
            float ys = ex[j] / sum;
            float hard = (j == bi) ? 1.f : 0.f;
            outRW[(size_t)tok * NE + j] = (hard + ys) - ys;
        }
        outIdx[tok] = (float)bi;
        g_eidx[tok] = bi;
        atomicAdd(&g_cnt[bi], 1);
        if (best - second < DELTA) {
            int p = atomicAdd(&g_nflag, 1);
            g_flag[p] = tok;
        }
    }
}

__global__ void set_nseg()
{
    if (threadIdx.x == 0) { g_nseg[0] = 0; g_nseg[1] = g_nflag; }
}

// ---------------- exact routing fix for flagged tokens (from exact h2) -----------
__global__ void routing_fix(const float* __restrict__ h2f, const float* __restrict__ rw3,
                            const float* __restrict__ rb3, const float* __restrict__ gumbel,
                            float* __restrict__ outRW, float* __restrict__ outIdx)
{
    int fi = blockIdx.x * 8 + (threadIdx.x >> 5);
    if (fi >= g_nflag) return;
    int lane = threadIdx.x & 31;
    int tok = g_flag[fi];
    const float* h = h2f + (size_t)fi * DH2;

    float acc[NE];
    #pragma unroll
    for (int j = 0; j < NE; j++) acc[j] = 0.f;
    #pragma unroll
    for (int i = 0; i < DH2 / 32; i++) {
        int k = lane + i * 32;
        float hv = h[k];
        #pragma unroll
        for (int j = 0; j < NE; j++)
            acc[j] = fmaf(hv, rw3[j * DH2 + k], acc[j]);
    }
    #pragma unroll
    for (int j = 0; j < NE; j++)
        #pragma unroll
        for (int o = 16; o; o >>= 1)
            acc[j] += __shfl_xor_sync(0xffffffffu, acc[j], o);

    if (lane == 0) {
        float z[NE];
        float best = -1e30f; int bi = 0;
        #pragma unroll
        for (int j = 0; j < NE; j++) {
            float lg = acc[j] + rb3[j];
            z[j] = (lg + gumbel[(size_t)tok * NE + j]) / 0.07f;
            if (z[j] > best) { best = z[j]; bi = j; }
        }
        float ex[NE], sum = 0.f;
        #pragma unroll
        for (int j = 0; j < NE; j++) { ex[j] = expf(z[j] - best); sum += ex[j]; }
        #pragma unroll
        for (int j = 0; j < NE; j++) {
            float ys = ex[j] / sum;
            float hard = (j == bi) ? 1.f : 0.f;
            outRW[(size_t)tok * NE + j] = (hard + ys) - ys;
        }
        outIdx[tok] = (float)bi;
        int old = g_eidx[tok];
        if (bi != old) {
            atomicSub(&g_cnt[old], 1);
            atomicAdd(&g_cnt[bi], 1);
            g_eidx[tok] = bi;
        }
    }
}

__global__ void scan_kernel()
{
    if (threadIdx.x == 0 && blockIdx.x == 0) {
        int o = 0;
        for (int e = 0; e < NE; e++) { g_off[e] = o; g_cur[e] = o; o += g_cnt[e]; }
        g_off[NE] = o;
    }
}

__global__ void fill_perm()
{
    int t = blockIdx.x * blockDim.x + threadIdx.x;
    if (t < BT) {
        int e = g_eidx[t];
        int p = atomicAdd(&g_cur[e], 1);
        g_perm[p]   = t;
        g_rowexp[p] = e;
    }
}

// ---------------- final: LN(Y + O) scattered back to token order ------------------
__global__ void final_kernel(const float* __restrict__ Y, const float* __restrict__ O,
                             const float* __restrict__ ng, const float* __restrict__ nb,
                             float* __restrict__ outMain)
{
    int r = blockIdx.x * 8 + (threadIdx.x >> 5);
    if (r >= BT) return;
    int lane = threadIdx.x & 31;
    int e = g_rowexp[r];
    int t = g_perm[r];

    float v[8];
    float s = 0.f;
    #pragma unroll
    for (int i = 0; i < 8; i++) {
        int c = lane + i * 32;
        v[i] = Y[(size_t)r * DOUT + c] + O[(size_t)r * DOUT + c];
        s += v[i];
    }
    #pragma unroll
    for (int o = 16; o; o >>= 1) s += __shfl_xor_sync(0xffffffffu, s, o);
    float mu = s / (float)DOUT;
    float sq = 0.f;
    #pragma unroll
    for (int i = 0; i < 8; i++) { float d = v[i] - mu; sq += d * d; }
    #pragma unroll
    for (int o = 16; o; o >>= 1) sq += __shfl_xor_sync(0xffffffffu, sq, o);
    float inv = 1.0f / sqrtf(sq / (float)DOUT + 1e-5f);

    const float* gp = ng + (long)e * DOUT;
    const float* bp = nb + (long)e * DOUT;
    float* op = outMain + (size_t)t * DOUT;
    #pragma unroll
    for (int i = 0; i < 8; i++) {
        int c = lane + i * 32;
        op[c] = (v[i] - mu) * inv * gp[c] + bp[c];
    }
}

// ---------------- launch ----------------------------------------------------------
extern "C" void kernel_launch(void* const* d_in, const int* in_sizes, int n_in,
                              void* d_out, int out_size)
{
    const float* x      = (const float*)d_in[0];
    const float* gumbel = (const float*)d_in[1];
    const float* rw1  = (const float*)d_in[2];
    const float* rb1  = (const float*)d_in[3];
    const float* rg1  = (const float*)d_in[4];
    const float* rbe1 = (const float*)d_in[5];
    const float* rw2  = (const float*)d_in[6];
    const float* rb2  = (const float*)d_in[7];
    const float* rg2  = (const float*)d_in[8];
    const float* rbe2 = (const float*)d_in[9];
    const float* rw3  = (const float*)d_in[10];
    const float* rb3  = (const float*)d_in[11];
    const float* ew1  = (const float*)d_in[12];
    const float* eb1  = (const float*)d_in[13];
    const float* eg1  = (const float*)d_in[14];
    const float* ebe1 = (const float*)d_in[15];
    const float* ew2  = (const float*)d_in[16];
    const float* eb2  = (const float*)d_in[17];
    const float* eg2  = (const float*)d_in[18];
    const float* ebe2 = (const float*)d_in[19];
    const float* ew3  = (const float*)d_in[20];
    const float* eb3  = (const float*)d_in[21];
    const float* eg3  = (const float*)d_in[22];
    const float* ebe3 = (const float*)d_in[23];
    const float* wqkv = (const float*)d_in[24];
    const float* bqkv = (const float*)d_in[25];
    const float* wo   = (const float*)d_in[26];
    const float* bo   = (const float*)d_in[27];
    const float* ng   = (const float*)d_in[28];
    const float* nb   = (const float*)d_in[29];

    float* outMain = (float*)d_out;
    float* outRW   = outMain + (size_t)BT * DOUT;
    float* outIdx  = outRW   + (size_t)BT * NE;

    float *bufA, *bufB, *Yb, *fA, *fB, *wc, *bc;
    int *off, *perm, *rowexp, *flag, *nseg; void *cntp, *nflagp;
    cudaGetSymbolAddress((void**)&bufA,   g_bufA);
    cudaGetSymbolAddress((void**)&bufB,   g_bufB);
    cudaGetSymbolAddress((void**)&Yb,     g_Y);
    cudaGetSymbolAddress((void**)&fA,     g_fA);
    cudaGetSymbolAddress((void**)&fB,     g_fB);
    cudaGetSymbolAddress((void**)&wc,     g_wc);
    cudaGetSymbolAddress((void**)&bc,     g_bc);
    cudaGetSymbolAddress((void**)&off,    g_off);
    cudaGetSymbolAddress((void**)&perm,   g_perm);
    cudaGetSymbolAddress((void**)&rowexp, g_rowexp);
    cudaGetSymbolAddress((void**)&flag,   g_flag);
    cudaGetSymbolAddress((void**)&nseg,   g_nseg);
    cudaGetSymbolAddress(&cntp,           g_cnt);
    cudaGetSymbolAddress(&nflagp,         g_nflag);

    cudaMemsetAsync(cntp, 0, NE * sizeof(int));
    cudaMemsetAsync(nflagp, 0, sizeof(int));
    fuse_wo_wv<<<dim3(1, DOUT, NE), 256>>>(wqkv, bqkv, wo, bo, wc, bc);

    // ---- router (plain tf32) ----
    gemm_tc<0><<<dim3(BT / BM, DH / BN, 1), 256>>>(x, nullptr, rw1, rb1, bufA, DH, DIN,
                                                   nullptr, 0, 0, BT);
    ln_rows<<<BT / 8, 256>>>(bufA, bufA, DH, rg1, rbe1, 0, 1, nullptr, BT, nullptr);
    gemm_tc<0><<<dim3(BT / BM, (DH2 + BN - 1) / BN, 1), 256>>>(bufA, nullptr, rw2, rb2, bufB,
                                                               DH2, DH, nullptr, 0, 0, BT);
    ln_rows<<<BT / 8, 256>>>(bufB, bufB, DH2, rg2, rbe2, 0, 1, nullptr, BT, nullptr);
    routing_kernel<<<BT / 8, 256>>>(bufB, rw3, rb3, gumbel, outRW, outIdx);
    set_nseg<<<1, 32>>>();

    // ---- exact recheck of flagged tokens via batched split-tf32 GEMMs ----
    gemm_tc<1><<<dim3(BT / BM, DH / BN, 1), 256>>>(x, flag, rw1, rb1, fA, DH, DIN,
                                                   nseg, 0, 0, BT);
    ln_rows<<<BT / 8, 256>>>(fA, fA, DH, rg1, rbe1, 0, 1, nullptr, BT, (const int*)nflagp);
    gemm_tc<1><<<dim3(BT / BM, (DH2 + BN - 1) / BN, 1), 256>>>(fA, nullptr, rw2, rb2, fB,
                                                               DH2, DH, nseg, 0, 0, BT);
    ln_rows<<<BT / 8, 256>>>(fB, fB, DH2, rg2, rbe2, 0, 1, nullptr, BT, (const int*)nflagp);
    routing_fix<<<BT / 8, 256>>>(fB, rw3, rb3, gumbel, outRW, outIdx);

    scan_kernel<<<1, 32>>>();
    fill_perm<<<BT / 256, 256>>>();

    // ---- experts (compacted; plain tf32) ----
    gemm_tc<0><<<dim3(BT / BM, DH / BN, NE), 256>>>(x, perm, ew1, eb1, bufA, DH, DIN,
                                                    off, (long)DH * DIN, DH, BT);
    ln_rows<<<BT / 8, 256>>>(bufA, bufA, DH, eg1, ebe1, DH, 1, rowexp, BT, nullptr);

    gemm_tc<0><<<dim3(BT / BM, DH / BN, NE), 256>>>(bufA, nullptr, ew2, eb2, bufB, DH, DH,
                                                    off, (long)DH * DH, DH, BT);
    ln_rows<<<BT / 8, 256>>>(bufB, bufB, DH, eg2, ebe2, DH, 1, rowexp, BT, nullptr);

    gemm_tc<0><<<dim3(BT / BM, DOUT / BN, NE), 256>>>(bufB, nullptr, ew3, eb3, Yb, DOUT, DH,
                                                      off, (long)DOUT * DH, DOUT, BT);
    ln_rows<<<BT / 8, 256>>>(Yb, Yb, DOUT, eg3, ebe3, DOUT, 0, rowexp, BT, nullptr);

    // attention over length-1 seq == V; V-proj and O-proj fused into wc/bc
    gemm_tc<0><<<dim3(BT / BM, DOUT / BN, NE), 256>>>(Yb, nullptr, wc, bc, bufA, DOUT, DOUT,
                                                      off, (long)DOUT * DOUT, DOUT, BT);

    final_kernel<<<BT / 8, 256>>>(Yb, bufA, ng, nb, outMain);
}

// round 6
// speedup vs baseline: 1.5839x; 1.0352x over previous
#include <cuda_runtime.h>
#include <cuda_bf16.h>
#include <mma.h>
#include <math.h>
#include <stdint.h>

using namespace nvcuda;

// Problem constants
#define BT   32768
#define DIN  768
#define DH   384
#define DH2  192
#define DOUT 256
#define NE   5
#define DELTA 0.35f

// GEMM tile config
#define BM 128
#define BN 128
#define BKK 16
#define LDS_PAD 20
#define STAGES 4
#define STAGE_FLOATS 5120        // (128*20)*2 tiles
#define STAGE_BYTES  20480
#define BOFF_BYTES   10240       // B tile offset within a stage
#define SMEM_BYTES   (STAGES * STAGE_BYTES)   // 81920

// ---------------- scratch (device globals) ----------------
__device__ float g_bufA[(size_t)BT * DH];
__device__ float g_bufB[(size_t)BT * DH];
__device__ float g_Y[(size_t)BT * DOUT];
__device__ float g_fA[(size_t)BT * DH];
__device__ float g_fB[(size_t)BT * DH2];
__device__ float g_wc[(size_t)NE * DOUT * DOUT];
__device__ float g_bc[NE * DOUT];
// tf32-pre-rounded weights
__device__ float g_rw1r[DH * DIN];
__device__ float g_rw2r[DH2 * DH];
__device__ float g_ew1r[(size_t)NE * DH * DIN];
__device__ float g_ew2r[(size_t)NE * DH * DH];
__device__ float g_ew3r[(size_t)NE * DOUT * DH];
__device__ int   g_eidx[BT];
__device__ int   g_perm[BT];
__device__ int   g_rowexp[BT];
__device__ int   g_cnt[NE];
__device__ int   g_off[NE + 1];
__device__ int   g_cur[NE];
__device__ int   g_flag[BT];
__device__ int   g_nflag;
__device__ int   g_nseg[2];

__device__ __forceinline__ float tf32r(float x) { return wmma::__float_to_tf32(x); }

__device__ __forceinline__ uint32_t smem_u32(const void* p) {
    uint32_t a;
    asm("{ .reg .u64 t; cvta.to.shared.u64 t, %1; cvt.u32.u64 %0, t; }" : "=r"(a) : "l"(p));
    return a;
}
__device__ __forceinline__ void cpasync16(uint32_t dst, const float* src) {
    asm volatile("{ .reg .u64 g; cvta.to.global.u64 g, %1;"
                 "cp.async.ca.shared.global [%0], [g], 16; }"
                 :: "r"(dst), "l"(src) : "memory");
}
#define CP_COMMIT() asm volatile("cp.async.commit_group;" ::: "memory")
#define CP_WAIT2()  asm volatile("cp.async.wait_group 2;" ::: "memory")
#define CP_WAIT0()  asm volatile("cp.async.wait_group 0;" ::: "memory")

// ============ tensor-core GEMM: C = A.W^T + bias ============
// SPLIT=1: 3-term split-tf32 (~2^-24) on RAW fp32 inputs — recheck path.
// SPLIT=0: plain tf32. RA=1: round A-fragments (A source is raw fp32);
//          B (weights) must be pre-rounded to tf32. RA=0: both pre-rounded.
// seg != nullptr => segmented (blockIdx.z); gather maps rows of A.
template<int SPLIT, int RA>
__global__ void __launch_bounds__(256, SPLIT ? 1 : 2)
gemm_tc(const float* __restrict__ A, const int* __restrict__ gather,
        const float* __restrict__ W, const float* __restrict__ bias,
        float* __restrict__ C, int N, int K,
        const int* __restrict__ seg, long wstride, int bstride, int Mtot)
{
    extern __shared__ float dsm[];

    int e = 0, rowbase = 0, segM = Mtot;
    if (seg) { e = blockIdx.z; rowbase = seg[e]; segM = seg[e + 1] - rowbase; }
    int mt = blockIdx.x * BM;
    if (mt >= segM) return;

    const float* Wp = W + (long)e * wstride;
    const float* bp = bias + (long)e * bstride;
    int n0 = blockIdx.y * BN;

    int tid = threadIdx.x;
    int wid = tid >> 5;
    int wm  = wid >> 1;
    int wn  = wid & 1;

    // loader geometry: 512 float4 per tile, 2 per thread
    int rA0 = tid >> 2,          cA0 = (tid & 3) * 4;
    int rA1 = (tid + 256) >> 2,  cA1 = cA0;
    int mr0 = mt + rA0; if (mr0 > segM - 1) mr0 = segM - 1;
    int mr1 = mt + rA1; if (mr1 > segM - 1) mr1 = segM - 1;
    int ar0 = gather ? gather[rowbase + mr0] : rowbase + mr0;
    int ar1 = gather ? gather[rowbase + mr1] : rowbase + mr1;
    const float* ap0 = A + (size_t)ar0 * K + cA0;
    const float* ap1 = A + (size_t)ar1 * K + cA1;
    int nr0 = n0 + rA0; if (nr0 > N - 1) nr0 = N - 1;
    int nr1 = n0 + rA1; if (nr1 > N - 1) nr1 = N - 1;
    const float* bpt0 = Wp + (size_t)nr0 * K + cA0;
    const float* bpt1 = Wp + (size_t)nr1 * K + cA1;

    uint32_t smb = smem_u32(dsm);
    uint32_t offA0 = (uint32_t)(rA0 * LDS_PAD + cA0) * 4;
    uint32_t offA1 = (uint32_t)(rA1 * LDS_PAD + cA1) * 4;

    int nk = K / BKK;

    auto issue = [&](int stage, int kb) {
        int k = kb * BKK;
        uint32_t base = smb + stage * STAGE_BYTES;
        cpasync16(base + offA0, ap0 + k);
        cpasync16(base + offA1, ap1 + k);
        cpasync16(base + BOFF_BYTES + offA0, bpt0 + k);
        cpasync16(base + BOFF_BYTES + offA1, bpt1 + k);
    };

    wmma::fragment<wmma::accumulator, 16, 16, 8, float> acc[2][4];
    #pragma unroll
    for (int mi = 0; mi < 2; mi++)
        #pragma unroll
        for (int ni = 0; ni < 4; ni++) wmma::fill_fragment(acc[mi][ni], 0.f);

    issue(0, 0); CP_COMMIT();
    issue(1, 1); CP_COMMIT();
    issue(2, 2); CP_COMMIT();

    for (int kb = 0; kb < nk; kb++) {
        CP_WAIT2();
        __syncthreads();
        int st = kb & 3;
        const float* sa = dsm + st * STAGE_FLOATS;
        const float* sb = sa + 2560;

        #pragma unroll
        for (int ks = 0; ks < 2; ks++) {
            wmma::fragment<wmma::matrix_a, 16, 16, 8, wmma::precision::tf32, wmma::row_major> a[2];
            wmma::fragment<wmma::matrix_b, 16, 16, 8, wmma::precision::tf32, wmma::col_major> b[4];
            #pragma unroll
            for (int mi = 0; mi < 2; mi++)
                wmma::load_matrix_sync(a[mi], sa + (wm * 32 + mi * 16) * LDS_PAD + ks * 8, LDS_PAD);
            #pragma unroll
            for (int ni = 0; ni < 4; ni++)
                wmma::load_matrix_sync(b[ni], sb + (wn * 64 + ni * 16) * LDS_PAD + ks * 8, LDS_PAD);

            if (SPLIT) {
                wmma::fragment<wmma::matrix_a, 16, 16, 8, wmma::precision::tf32, wmma::row_major> ah[2];
                wmma::fragment<wmma::matrix_b, 16, 16, 8, wmma::precision::tf32, wmma::col_major> bh[4];
                #pragma unroll
                for (int mi = 0; mi < 2; mi++)
                    #pragma unroll
                    for (int i = 0; i < a[mi].num_elements; i++) {
                        float h = tf32r(a[mi].x[i]);
                        ah[mi].x[i] = h;
                        a[mi].x[i] = tf32r(a[mi].x[i] - h);
                    }
                #pragma unroll
                for (int ni = 0; ni < 4; ni++)
                    #pragma unroll
                    for (int i = 0; i < b[ni].num_elements; i++) {
                        float h = tf32r(b[ni].x[i]);
                        bh[ni].x[i] = h;
                        b[ni].x[i] = tf32r(b[ni].x[i] - h);
                    }
                #pragma unroll
                for (int mi = 0; mi < 2; mi++)
                    #pragma unroll
                    for (int ni = 0; ni < 4; ni++) {
                        wmma::mma_sync(acc[mi][ni], ah[mi], bh[ni], acc[mi][ni]);
                        wmma::mma_sync(acc[mi][ni], ah[mi], b[ni],  acc[mi][ni]);
                        wmma::mma_sync(acc[mi][ni], a[mi],  bh[ni], acc[mi][ni]);
                    }
            } else {
                if (RA) {
                    #pragma unroll
                    for (int mi = 0; mi < 2; mi++)
                        #pragma unroll
                        for (int i = 0; i < a[mi].num_elements; i++)
                            a[mi].x[i] = tf32r(a[mi].x[i]);
                }
                #pragma unroll
                for (int mi = 0; mi < 2; mi++)
                    #pragma unroll
                    for (int ni = 0; ni < 4; ni++)
                        wmma::mma_sync(acc[mi][ni], a[mi], b[ni], acc[mi][ni]);
            }
        }

        int nkb = kb + 3;
        if (nkb < nk) issue(nkb & 3, nkb);
        CP_COMMIT();
    }

    // ---- epilogue: stage 64 rows through smem, add bias ----
    CP_WAIT0();
    __syncthreads();
    float* stage = dsm;
    const int SLD = 132;
    #pragma unroll
    for (int r = 0; r < 2; r++) {
        if ((wm >> 1) == r) {
            #pragma unroll
            for (int mi = 0; mi < 2; mi++)
                #pragma unroll
                for (int ni = 0; ni < 4; ni++)
                    wmma::store_matrix_sync(stage + ((wm & 1) * 32 + mi * 16) * SLD + wn * 64 + ni * 16,
                                            acc[mi][ni], SLD, wmma::mem_row_major);
        }
        __syncthreads();
        #pragma unroll
        for (int it = 0; it < 8; it++) {
            int fidx = tid + it * 256;
            int lrow = fidx >> 5;
            int c4 = (fidx & 31) * 4;
            int m = mt + r * 64 + lrow;
            int n = n0 + c4;
            if (m < segM && n < N) {
                float4 v = *(float4*)(stage + lrow * SLD + c4);
                float4 bv = *(const float4*)(bp + n);
                v.x += bv.x; v.y += bv.y; v.z += bv.z; v.w += bv.w;
                *(float4*)(C + (size_t)(rowbase + m) * N + n) = v;
            }
        }
        __syncthreads();
    }
}

// ---------------- weight pre-rounding (once per launch, tiny) --------------------
__global__ void round_weights(const float* __restrict__ src, float* __restrict__ dst, int n)
{
    int i = blockIdx.x * blockDim.x + threadIdx.x;
    if (i < n) dst[i] = tf32r(src[i]);
}

// ---------------- fuse wo @ wv (tf32-rounded output: used only as GEMM B) --------
__global__ void fuse_wo_wv(const float* __restrict__ wqkv, const float* __restrict__ bqkv,
                           const float* __restrict__ wo, const float* __restrict__ bo,
                           float* __restrict__ wc, float* __restrict__ bc)
{
    int e = blockIdx.z, n = blockIdx.y, k = threadIdx.x;
    const float* woR = wo + ((size_t)e * DOUT + n) * DOUT;
    const float* wv  = wqkv + (size_t)e * 3 * DOUT * DOUT + 2 * DOUT * DOUT;
    const float* bv  = bqkv + (size_t)e * 3 * DOUT + 2 * DOUT;
    float s = 0.f;
    for (int j = 0; j < DOUT; j++) s = fmaf(woR[j], wv[(size_t)j * DOUT + k], s);
    wc[((size_t)e * DOUT + n) * DOUT + k] = tf32r(s);
    if (k == 0) {
        float sb = bo[e * DOUT + n];
        for (int j = 0; j < DOUT; j++) sb = fmaf(woR[j], bv[j], sb);
        bc[e * DOUT + n] = sb;
    }
}

// ---------------- row LayerNorm (+optional ReLU, optional tf32-round out) --------
__global__ void ln_rows(const float* __restrict__ in, float* __restrict__ out, int Ncols,
                        const float* __restrict__ g, const float* __restrict__ b,
                        int gstride, int doRelu, const int* __restrict__ rowexp, int M,
                        const int* __restrict__ Mdev, int roundOut)
{
    int row = blockIdx.x * 8 + (threadIdx.x >> 5);
    int Mr = Mdev ? *Mdev : M;
    if (row >= Mr) return;
    int lane = threadIdx.x & 31;
    int e = rowexp ? rowexp[row] : 0;
    const float* ip = in + (size_t)row * Ncols;
    int nw = Ncols >> 5;

    float v[12];
    float s = 0.f;
    for (int i = 0; i < nw; i++) { v[i] = ip[lane + i * 32]; s += v[i]; }
    #pragma unroll
    for (int o = 16; o; o >>= 1) s += __shfl_xor_sync(0xffffffffu, s, o);
    float mu = s / (float)Ncols;

    float sq = 0.f;
    for (int i = 0; i < nw; i++) { float d = v[i] - mu; sq += d * d; }
    #pragma unroll
    for (int o = 16; o; o >>= 1) sq += __shfl_xor_sync(0xffffffffu, sq, o);
    float inv = 1.0f / sqrtf(sq / (float)Ncols + 1e-5f);

    const float* gp = g + (long)e * gstride;
    const float* bp = b + (long)e * gstride;
    float* op = out + (size_t)row * Ncols;
    for (int i = 0; i < nw; i++) {
        int c = lane + i * 32;
        float o2 = (v[i] - mu) * inv * gp[c] + bp[c];
        if (doRelu) o2 = fmaxf(o2, 0.f);
        if (roundOut) o2 = tf32r(o2);
        op[c] = o2;
    }
}

// ---------------- router head: provisional + ambiguity flagging -------------------
__global__ void routing_kernel(const float* __restrict__ h2, const float* __restrict__ rw3,
                               const float* __restrict__ rb3, const float* __restrict__ gumbel,
                               float* __restrict__ outRW, float* __restrict__ outIdx)
{
    int tok = blockIdx.x * 8 + (threadIdx.x >> 5);
    if (tok >= BT) return;
    int lane = threadIdx.x & 31;
    const float* h = h2 + (size_t)tok * DH2;

    float acc[NE];
    #pragma unroll
    for (int j = 0; j < NE; j++) acc[j] = 0.f;
    #pragma unroll
    for (int i = 0; i < DH2 / 32; i++) {
        int k = lane + i * 32;
        float hv = h[k];
        #pragma unroll
        for (int j = 0; j < NE; j++)
            acc[j] = fmaf(hv, rw3[j * DH2 + k], acc[j]);
    }
    #pragma unroll
    for (int j = 0; j < NE; j++)
        #pragma unroll
        for (int o = 16; o; o >>= 1)
            acc[j] += __shfl_xor_sync(0xffffffffu, acc[j], o);

    if (lane == 0) {
        float z[NE];
        float best = -1e30f, second = -1e30f; int bi = 0;
        #pragma unroll
        for (int j = 0; j < NE; j++) {
            float lg = acc[j] + rb3[j];
            z[j] = (lg + gumbel[(size_t)tok * NE + j]) / 0.07f;
            if (z[j] > best) { second = best; best = z[j]; bi = j; }
            else if (z[j] > second) second = z[j];
        }
        float ex[NE], sum = 0.f;
        #pragma unroll
        for (int j = 0; j < NE; j++) { ex[j] = expf(z[j] - best); sum += ex[j]; }
        #pragma unroll
        for (int j = 0; j < NE; j++) {
            float ys = ex[j] / sum;
            float hard = (j == bi) ? 1.f : 0.f;
            outRW[(size_t)tok * NE + j] = (hard + ys) - ys;
        }
        outIdx[tok] = (float)bi;
        g_eidx[tok] = bi;
        atomicAdd(&g_cnt[bi], 1);
        if (best - second < DELTA) {
            int p = atomicAdd(&g_nflag, 1);
            g_flag[p] = tok;
        }
    }
}

__global__ void set_nseg()
{
    if (threadIdx.x == 0) { g_nseg[0] = 0; g_nseg[1] = g_nflag; }
}

// ---------------- exact routing fix for flagged tokens ---------------------------
__global__ void routing_fix(const float* __restrict__ h2f, const float* __restrict__ rw3,
                            const float* __restrict__ rb3, const float* __restrict__ gumbel,
                            float* __restrict__ outRW, float* __restrict__ outIdx)
{
    int fi = blockIdx.x * 8 + (threadIdx.x >> 5);
    if (fi >= g_nflag) return;
    int lane = threadIdx.x & 31;
    int tok = g_flag[fi];
    const float* h = h2f + (size_t)fi * DH2;

    float acc[NE];
    #pragma unroll
    for (int j = 0; j < NE; j++) acc[j] = 0.f;
    #pragma unroll
    for (int i = 0; i < DH2 / 32; i++) {
        int k = lane + i * 32;
        float hv = h[k];
        #pragma unroll
        for (int j = 0; j < NE; j++)
            acc[j] = fmaf(hv, rw3[j * DH2 + k], acc[j]);
    }
    #pragma unroll
    for (int j = 0; j < NE; j++)
        #pragma unroll
        for (int o = 16; o; o >>= 1)
            acc[j] += __shfl_xor_sync(0xffffffffu, acc[j], o);

    if (lane == 0) {
        float z[NE];
        float best = -1e30f; int bi = 0;
        #pragma unroll
        for (int j = 0; j < NE; j++) {
            float lg = acc[j] + rb3[j];
            z[j] = (lg + gumbel[(size_t)tok * NE + j]) / 0.07f;
            if (z[j] > best) { best = z[j]; bi = j; }
        }
        float ex[NE], sum = 0.f;
        #pragma unroll
        for (int j = 0; j < NE; j++) { ex[j] = expf(z[j] - best); sum += ex[j]; }
        #pragma unroll
        for (int j = 0; j < NE; j++) {
            float ys = ex[j] / sum;
            float hard = (j == bi) ? 1.f : 0.f;
            outRW[(size_t)tok * NE + j] = (hard + ys) - ys;
        }
        outIdx[tok] = (float)bi;
        int old = g_eidx[tok];
        if (bi != old) {
            atomicSub(&g_cnt[old], 1);
            atomicAdd(&g_cnt[bi], 1);
            g_eidx[tok] = bi;
        }
    }
}

__global__ void scan_kernel()
{
    if (threadIdx.x == 0 && blockIdx.x == 0) {
        int o = 0;
        for (int e = 0; e < NE; e++) { g_off[e] = o; g_cur[e] = o; o += g_cnt[e]; }
        g_off[NE] = o;
    }
}

__global__ void fill_perm()
{
    int t = blockIdx.x * blockDim.x + threadIdx.x;
    if (t < BT) {
        int e = g_eidx[t];
        int p = atomicAdd(&g_cur[e], 1);
        g_perm[p]   = t;
        g_rowexp[p] = e;
    }
}

// ---------------- final: LN(Y + O) scattered back to token order ------------------
__global__ void final_kernel(const float* __restrict__ Y, const float* __restrict__ O,
                             const float* __restrict__ ng, const float* __restrict__ nb,
                             float* __restrict__ outMain)
{
    int r = blockIdx.x * 8 + (threadIdx.x >> 5);
    if (r >= BT) return;
    int lane = threadIdx.x & 31;
    int e = g_rowexp[r];
    int t = g_perm[r];

    float v[8];
    float s = 0.f;
    #pragma unroll
    for (int i = 0; i < 8; i++) {
        int c = lane + i * 32;
        v[i] = Y[(size_t)r * DOUT + c] + O[(size_t)r * DOUT + c];
        s += v[i];
    }
    #pragma unroll
    for (int o = 16; o; o >>= 1) s += __shfl_xor_sync(0xffffffffu, s, o);
    float mu = s / (float)DOUT;
    float sq = 0.f;
    #pragma unroll
    for (int i = 0; i < 8; i++) { float d = v[i] - mu; sq += d * d; }
    #pragma unroll
    for (int o = 16; o; o >>= 1) sq += __shfl_xor_sync(0xffffffffu, sq, o);
    float inv = 1.0f / sqrtf(sq / (float)DOUT + 1e-5f);

    const float* gp = ng + (long)e * DOUT;
    const float* bp = nb + (long)e * DOUT;
    float* op = outMain + (size_t)t * DOUT;
    #pragma unroll
    for (int i = 0; i < 8; i++) {
        int c = lane + i * 32;
        op[c] = (v[i] - mu) * inv * gp[c] + bp[c];
    }
}

// ---------------- launch ----------------------------------------------------------
extern "C" void kernel_launch(void* const* d_in, const int* in_sizes, int n_in,
                              void* d_out, int out_size)
{
    const float* x      = (const float*)d_in[0];
    const float* gumbel = (const float*)d_in[1];
    const float* rw1  = (const float*)d_in[2];
    const float* rb1  = (const float*)d_in[3];
    const float* rg1  = (const float*)d_in[4];
    const float* rbe1 = (const float*)d_in[5];
    const float* rw2  = (const float*)d_in[6];
    const float* rb2  = (const float*)d_in[7];
    const float* rg2  = (const float*)d_in[8];
    const float* rbe2 = (const float*)d_in[9];
    const float* rw3  = (const float*)d_in[10];
    const float* rb3  = (const float*)d_in[11];
    const float* ew1  = (const float*)d_in[12];
    const float* eb1  = (const float*)d_in[13];
    const float* eg1  = (const float*)d_in[14];
    const float* ebe1 = (const float*)d_in[15];
    const float* ew2  = (const float*)d_in[16];
    const float* eb2  = (const float*)d_in[17];
    const float* eg2  = (const float*)d_in[18];
    const float* ebe2 = (const float*)d_in[19];
    const float* ew3  = (const float*)d_in[20];
    const float* eb3  = (const float*)d_in[21];
    const float* eg3  = (const float*)d_in[22];
    const float* ebe3 = (const float*)d_in[23];
    const float* wqkv = (const float*)d_in[24];
    const float* bqkv = (const float*)d_in[25];
    const float* wo   = (const float*)d_in[26];
    const float* bo   = (const float*)d_in[27];
    const float* ng   = (const float*)d_in[28];
    const float* nb   = (const float*)d_in[29];

    float* outMain = (float*)d_out;
    float* outRW   = outMain + (size_t)BT * DOUT;
    float* outIdx  = outRW   + (size_t)BT * NE;

    float *bufA, *bufB, *Yb, *fA, *fB, *wc, *bc;
    float *rw1r, *rw2r, *ew1r, *ew2r, *ew3r;
    int *off, *perm, *rowexp, *flag, *nseg; void *cntp, *nflagp;
    cudaGetSymbolAddress((void**)&bufA,   g_bufA);
    cudaGetSymbolAddress((void**)&bufB,   g_bufB);
    cudaGetSymbolAddress((void**)&Yb,     g_Y);
    cudaGetSymbolAddress((void**)&fA,     g_fA);
    cudaGetSymbolAddress((void**)&fB,     g_fB);
    cudaGetSymbolAddress((void**)&wc,     g_wc);
    cudaGetSymbolAddress((void**)&bc,     g_bc);
    cudaGetSymbolAddress((void**)&rw1r,   g_rw1r);
    cudaGetSymbolAddress((void**)&rw2r,   g_rw2r);
    cudaGetSymbolAddress((void**)&ew1r,   g_ew1r);
    cudaGetSymbolAddress((void**)&ew2r,   g_ew2r);
    cudaGetSymbolAddress((void**)&ew3r,   g_ew3r);
    cudaGetSymbolAddress((void**)&off,    g_off);
    cudaGetSymbolAddress((void**)&perm,   g_perm);
    cudaGetSymbolAddress((void**)&rowexp, g_rowexp);
    cudaGetSymbolAddress((void**)&flag,   g_flag);
    cudaGetSymbolAddress((void**)&nseg,   g_nseg);
    cudaGetSymbolAddress(&cntp,           g_cnt);
    cudaGetSymbolAddress(&nflagp,         g_nflag);

    cudaFuncSetAttribute((const void*)gemm_tc<0,0>, cudaFuncAttributeMaxDynamicSharedMemorySize, SMEM_BYTES);
    cudaFuncSetAttribute((const void*)gemm_tc<0,1>, cudaFuncAttributeMaxDynamicSharedMemorySize, SMEM_BYTES);
    cudaFuncSetAttribute((const void*)gemm_tc<1,0>, cudaFuncAttributeMaxDynamicSharedMemorySize, SMEM_BYTES);

    cudaMemsetAsync(cntp, 0, NE * sizeof(int));
    cudaMemsetAsync(nflagp, 0, sizeof(int));

    // one-time prep: round weights to tf32, fuse wo@wv
    round_weights<<<(DH * DIN + 255) / 256, 256>>>(rw1, rw1r, DH * DIN);
    round_weights<<<(DH2 * DH + 255) / 256, 256>>>(rw2, rw2r, DH2 * DH);
    round_weights<<<(NE * DH * DIN + 255) / 256, 256>>>(ew1, ew1r, NE * DH * DIN);
    round_weights<<<(NE * DH * DH + 255) / 256, 256>>>(ew2, ew2r, NE * DH * DH);
    round_weights<<<(NE * DOUT * DH + 255) / 256, 256>>>(ew3, ew3r, NE * DOUT * DH);
    fuse_wo_wv<<<dim3(1, DOUT, NE), 256>>>(wqkv, bqkv, wo, bo, wc, bc);

    // ---- router (plain tf32) ----
    gemm_tc<0,1><<<dim3(BT / BM, DH / BN, 1), 256, SMEM_BYTES>>>(
        x, nullptr, rw1r, rb1, bufA, DH, DIN, nullptr, 0, 0, BT);
    ln_rows<<<BT / 8, 256>>>(bufA, bufA, DH, rg1, rbe1, 0, 1, nullptr, BT, nullptr, 1);
    gemm_tc<0,0><<<dim3(BT / BM, 2, 1), 256, SMEM_BYTES>>>(
        bufA, nullptr, rw2r, rb2, bufB, DH2, DH, nullptr, 0, 0, BT);
    ln_rows<<<BT / 8, 256>>>(bufB, bufB, DH2, rg2, rbe2, 0, 1, nullptr, BT, nullptr, 0);
    routing_kernel<<<BT / 8, 256>>>(bufB, rw3, rb3, gumbel, outRW, outIdx);
    set_nseg<<<1, 32>>>();

    // ---- exact recheck of flagged tokens (split-tf32 on RAW inputs) ----
    gemm_tc<1,0><<<dim3(BT / BM, DH / BN, 1), 256, SMEM_BYTES>>>(
        x, flag, rw1, rb1, fA, DH, DIN, nseg, 0, 0, BT);
    ln_rows<<<BT / 8, 256>>>(fA, fA, DH, rg1, rbe1, 0, 1, nullptr, BT, (const int*)nflagp, 0);
    gemm_tc<1,0><<<dim3(BT / BM, 2, 1), 256, SMEM_BYTES>>>(
        fA, nullptr, rw2, rb2, fB, DH2, DH, nseg, 0, 0, BT);
    ln_rows<<<BT / 8, 256>>>(fB, fB, DH2, rg2, rbe2, 0, 1, nullptr, BT, (const int*)nflagp, 0);
    routing_fix<<<BT / 8, 256>>>(fB, rw3, rb3, gumbel, outRW, outIdx);

    scan_kernel<<<1, 32>>>();
    fill_perm<<<BT / 256, 256>>>();

    // ---- experts (compacted; plain tf32) ----
    gemm_tc<0,1><<<dim3(BT / BM, DH / BN, NE), 256, SMEM_BYTES>>>(
        x, perm, ew1r, eb1, bufA, DH, DIN, off, (long)DH * DIN, DH, BT);
    ln_rows<<<BT / 8, 256>>>(bufA, bufA, DH, eg1, ebe1, DH, 1, rowexp, BT, nullptr, 1);

    gemm_tc<0,0><<<dim3(BT / BM, DH / BN, NE), 256, SMEM_BYTES>>>(
        bufA, nullptr, ew2r, eb2, bufB, DH, DH, off, (long)DH * DH, DH, BT);
    ln_rows<<<BT / 8, 256>>>(bufB, bufB, DH, eg2, ebe2, DH, 1, rowexp, BT, nullptr, 1);

    gemm_tc<0,0><<<dim3(BT / BM, DOUT / BN, NE), 256, SMEM_BYTES>>>(
        bufB, nullptr, ew3r, eb3, Yb, DOUT, DH, off, (long)DOUT * DH, DOUT, BT);
    ln_rows<<<BT / 8, 256>>>(Yb, Yb, DOUT, eg3, ebe3, DOUT, 0, rowexp, BT, nullptr, 0);

    // attention over length-1 seq == V; V-proj and O-proj fused into wc/bc
    gemm_tc<0,1><<<dim3(BT / BM, DOUT / BN, NE), 256, SMEM_BYTES>>>(
        Yb, nullptr, wc, bc, bufA, DOUT, DOUT, off, (long)DOUT * DOUT, DOUT, BT);

    final_kernel<<<BT / 8, 256>>>(Yb, bufA, ng, nb, outMain);
}

// round 7
// speedup vs baseline: 3.0168x; 1.9047x over previous
#include <cuda_runtime.h>
#include <cuda_fp16.h>
#include <mma.h>
#include <math.h>
#include <stdint.h>

using namespace nvcuda;

// Problem constants
#define BT   32768
#define DIN  768
#define DH   384
#define DH2  192
#define DOUT 256
#define NE   5
#define DELTA 0.35f

// ---- fp16 GEMM tile config (BM=BN=128, BK=32) ----
#define HPAD 40                   // halves per smem row (32 data + 8 pad)
#define HTILE_HALVES 5120         // 128*40
#define HSTAGE_BYTES 20480        // A tile + B tile (10240 each)
#define HBOFF 10240
#define HSMEM (4 * HSTAGE_BYTES)  // 81920

// ---- tf32 split GEMM config (recheck path) ----
#define LDS_PAD 20
#define TSTAGE_FLOATS 5120
#define TSTAGE_BYTES  20480
#define TBOFF_BYTES   10240
#define TSMEM (4 * TSTAGE_BYTES)

// ---------------- scratch (device globals) ----------------
__device__ float  g_bufA[(size_t)BT * DH];
__device__ float  g_bufB[(size_t)BT * DH];
__device__ float  g_Y[(size_t)BT * DOUT];
__device__ float  g_fA[(size_t)BT * DH];
__device__ float  g_fB[(size_t)BT * DH2];
__device__ float  g_bc[NE * DOUT];
// fp16 buffers
__device__ __half g_x16[(size_t)BT * DIN];
__device__ __half g_t16a[(size_t)BT * DH];
__device__ __half g_t16b[(size_t)BT * DH];
__device__ __half g_y16[(size_t)BT * DOUT];
__device__ __half g_wch[(size_t)NE * DOUT * DOUT];
__device__ __half g_rw1h[DH * DIN];
__device__ __half g_rw2h[DH2 * DH];
__device__ __half g_ew1h[(size_t)NE * DH * DIN];
__device__ __half g_ew2h[(size_t)NE * DH * DH];
__device__ __half g_ew3h[(size_t)NE * DOUT * DH];
__device__ int    g_eidx[BT];
__device__ int    g_perm[BT];
__device__ int    g_rowexp[BT];
__device__ int    g_cnt[NE];
__device__ int    g_off[NE + 1];
__device__ int    g_cur[NE];
__device__ int    g_flag[BT];
__device__ int    g_nflag;
__device__ int    g_nseg[2];

__device__ __forceinline__ float tf32r(float x) { return wmma::__float_to_tf32(x); }

__device__ __forceinline__ uint32_t smem_u32(const void* p) {
    uint32_t a;
    asm("{ .reg .u64 t; cvta.to.shared.u64 t, %1; cvt.u32.u64 %0, t; }" : "=r"(a) : "l"(p));
    return a;
}
__device__ __forceinline__ void cpasync16(uint32_t dst, const void* src) {
    asm volatile("{ .reg .u64 g; cvta.to.global.u64 g, %1;"
                 "cp.async.ca.shared.global [%0], [g], 16; }"
                 :: "r"(dst), "l"(src) : "memory");
}
#define CP_COMMIT() asm volatile("cp.async.commit_group;" ::: "memory")
#define CP_WAIT2()  asm volatile("cp.async.wait_group 2;" ::: "memory")
#define CP_WAIT0()  asm volatile("cp.async.wait_group 0;" ::: "memory")

// ================= fp16 tensor-core GEMM: C = A.W^T + bias (fp32 out) =============
// A, W in fp16 (pre-converted). fp32 accumulate. BM=128,BN=128,BK=32, 4-stage cp.async.
// seg != nullptr => segmented (blockIdx.z); gather maps rows of A.
__global__ void __launch_bounds__(256, 2)
gemm_h(const __half* __restrict__ A, const int* __restrict__ gather,
       const __half* __restrict__ W, const float* __restrict__ bias,
       float* __restrict__ C, int N, int K,
       const int* __restrict__ seg, long wstride, int bstride, int Mtot)
{
    extern __shared__ char hsm[];

    int e = 0, rowbase = 0, segM = Mtot;
    if (seg) { e = blockIdx.z; rowbase = seg[e]; segM = seg[e + 1] - rowbase; }
    int mt = blockIdx.x * 128;
    if (mt >= segM) return;

    const __half* Wp = W + (long)e * wstride;
    const float*  bp = bias + (long)e * bstride;
    int n0 = blockIdx.y * 128;

    int tid = threadIdx.x;
    int wid = tid >> 5;
    int wm  = wid >> 1;
    int wn  = wid & 1;

    // loader: per tile 128 rows x 4 chunks(16B=8 halves); 2 chunks/thread/tile
    int r0 = tid >> 2,         c0 = (tid & 3) * 8;
    int r1 = (tid + 256) >> 2, c1 = c0;
    int mr0 = mt + r0; if (mr0 > segM - 1) mr0 = segM - 1;
    int mr1 = mt + r1; if (mr1 > segM - 1) mr1 = segM - 1;
    int ar0 = gather ? gather[rowbase + mr0] : rowbase + mr0;
    int ar1 = gather ? gather[rowbase + mr1] : rowbase + mr1;
    const __half* ap0 = A + (size_t)ar0 * K + c0;
    const __half* ap1 = A + (size_t)ar1 * K + c1;
    int nr0 = n0 + r0; if (nr0 > N - 1) nr0 = N - 1;
    int nr1 = n0 + r1; if (nr1 > N - 1) nr1 = N - 1;
    const __half* bpt0 = Wp + (size_t)nr0 * K + c0;
    const __half* bpt1 = Wp + (size_t)nr1 * K + c1;

    uint32_t smb = smem_u32(hsm);
    uint32_t off0 = (uint32_t)(r0 * HPAD + c0) * 2;
    uint32_t off1 = (uint32_t)(r1 * HPAD + c1) * 2;

    int nk = K / 32;

    auto issue = [&](int stage, int kb) {
        int k = kb * 32;
        uint32_t base = smb + stage * HSTAGE_BYTES;
        cpasync16(base + off0, ap0 + k);
        cpasync16(base + off1, ap1 + k);
        cpasync16(base + HBOFF + off0, bpt0 + k);
        cpasync16(base + HBOFF + off1, bpt1 + k);
    };

    wmma::fragment<wmma::accumulator, 16, 16, 16, float> acc[2][4];
    #pragma unroll
    for (int mi = 0; mi < 2; mi++)
        #pragma unroll
        for (int ni = 0; ni < 4; ni++) wmma::fill_fragment(acc[mi][ni], 0.f);

    issue(0, 0); CP_COMMIT();
    issue(1, 1); CP_COMMIT();
    issue(2, 2); CP_COMMIT();

    for (int kb = 0; kb < nk; kb++) {
        CP_WAIT2();
        __syncthreads();
        int st = kb & 3;
        const __half* sa = (const __half*)(hsm + st * HSTAGE_BYTES);
        const __half* sb = sa + HTILE_HALVES;

        #pragma unroll
        for (int ks = 0; ks < 2; ks++) {
            wmma::fragment<wmma::matrix_a, 16, 16, 16, __half, wmma::row_major> a[2];
            wmma::fragment<wmma::matrix_b, 16, 16, 16, __half, wmma::col_major> b[4];
            #pragma unroll
            for (int mi = 0; mi < 2; mi++)
                wmma::load_matrix_sync(a[mi], sa + (wm * 32 + mi * 16) * HPAD + ks * 16, HPAD);
            #pragma unroll
            for (int ni = 0; ni < 4; ni++)
                wmma::load_matrix_sync(b[ni], sb + (wn * 64 + ni * 16) * HPAD + ks * 16, HPAD);
            #pragma unroll
            for (int mi = 0; mi < 2; mi++)
                #pragma unroll
                for (int ni = 0; ni < 4; ni++)
                    wmma::mma_sync(acc[mi][ni], a[mi], b[ni], acc[mi][ni]);
        }

        int nkb = kb + 3;
        if (nkb < nk) issue(nkb & 3, nkb);
        CP_COMMIT();
    }

    // epilogue: stage 64 rows through smem, add bias, write fp32
    CP_WAIT0();
    __syncthreads();
    float* stage = (float*)hsm;
    const int SLD = 132;
    #pragma unroll
    for (int r = 0; r < 2; r++) {
        if ((wm >> 1) == r) {
            #pragma unroll
            for (int mi = 0; mi < 2; mi++)
                #pragma unroll
                for (int ni = 0; ni < 4; ni++)
                    wmma::store_matrix_sync(stage + ((wm & 1) * 32 + mi * 16) * SLD + wn * 64 + ni * 16,
                                            acc[mi][ni], SLD, wmma::mem_row_major);
        }
        __syncthreads();
        #pragma unroll
        for (int it = 0; it < 8; it++) {
            int fidx = tid + it * 256;
            int lrow = fidx >> 5;
            int c4 = (fidx & 31) * 4;
            int m = mt + r * 64 + lrow;
            int n = n0 + c4;
            if (m < segM && n < N) {
                float4 v = *(float4*)(stage + lrow * SLD + c4);
                float4 bv = *(const float4*)(bp + n);
                v.x += bv.x; v.y += bv.y; v.z += bv.z; v.w += bv.w;
                *(float4*)(C + (size_t)(rowbase + m) * N + n) = v;
            }
        }
        __syncthreads();
    }
}

// ============ split-tf32 GEMM (~2^-24) — exact recheck path only ==================
__global__ void __launch_bounds__(256, 1)
gemm_split(const float* __restrict__ A, const int* __restrict__ gather,
           const float* __restrict__ W, const float* __restrict__ bias,
           float* __restrict__ C, int N, int K,
           const int* __restrict__ seg, int Mtot)
{
    extern __shared__ float tsm[];

    int rowbase = 0, segM = Mtot;
    if (seg) { rowbase = seg[0]; segM = seg[1] - rowbase; }
    int mt = blockIdx.x * 128;
    if (mt >= segM) return;

    const float* bp = bias;
    int n0 = blockIdx.y * 128;

    int tid = threadIdx.x;
    int wid = tid >> 5;
    int wm  = wid >> 1;
    int wn  = wid & 1;

    int rA0 = tid >> 2,         cA0 = (tid & 3) * 4;
    int rA1 = (tid + 256) >> 2, cA1 = cA0;
    int mr0 = mt + rA0; if (mr0 > segM - 1) mr0 = segM - 1;
    int mr1 = mt + rA1; if (mr1 > segM - 1) mr1 = segM - 1;
    int ar0 = gather ? gather[rowbase + mr0] : rowbase + mr0;
    int ar1 = gather ? gather[rowbase + mr1] : rowbase + mr1;
    const float* ap0 = A + (size_t)ar0 * K + cA0;
    const float* ap1 = A + (size_t)ar1 * K + cA1;
    int nr0 = n0 + rA0; if (nr0 > N - 1) nr0 = N - 1;
    int nr1 = n0 + rA1; if (nr1 > N - 1) nr1 = N - 1;
    const float* bpt0 = W + (size_t)nr0 * K + cA0;
    const float* bpt1 = W + (size_t)nr1 * K + cA1;

    uint32_t smb = smem_u32(tsm);
    uint32_t offA0 = (uint32_t)(rA0 * LDS_PAD + cA0) * 4;
    uint32_t offA1 = (uint32_t)(rA1 * LDS_PAD + cA1) * 4;

    int nk = K / 16;

    auto issue = [&](int stage, int kb) {
        int k = kb * 16;
        uint32_t base = smb + stage * TSTAGE_BYTES;
        cpasync16(base + offA0, ap0 + k);
        cpasync16(base + offA1, ap1 + k);
        cpasync16(base + TBOFF_BYTES + offA0, bpt0 + k);
        cpasync16(base + TBOFF_BYTES + offA1, bpt1 + k);
    };

    wmma::fragment<wmma::accumulator, 16, 16, 8, float> acc[2][4];
    #pragma unroll
    for (int mi = 0; mi < 2; mi++)
        #pragma unroll
        for (int ni = 0; ni < 4; ni++) wmma::fill_fragment(acc[mi][ni], 0.f);

    issue(0, 0); CP_COMMIT();
    issue(1, 1); CP_COMMIT();
    issue(2, 2); CP_COMMIT();

    for (int kb = 0; kb < nk; kb++) {
        CP_WAIT2();
        __syncthreads();
        int st = kb & 3;
        const float* sa = tsm + st * TSTAGE_FLOATS;
        const float* sb = sa + 2560;

        #pragma unroll
        for (int ks = 0; ks < 2; ks++) {
            wmma::fragment<wmma::matrix_a, 16, 16, 8, wmma::precision::tf32, wmma::row_major> a[2], ah[2];
            wmma::fragment<wmma::matrix_b, 16, 16, 8, wmma::precision::tf32, wmma::col_major> b[4], bh[4];
            #pragma unroll
            for (int mi = 0; mi < 2; mi++)
                wmma::load_matrix_sync(a[mi], sa + (wm * 32 + mi * 16) * LDS_PAD + ks * 8, LDS_PAD);
            #pragma unroll
            for (int ni = 0; ni < 4; ni++)
                wmma::load_matrix_sync(b[ni], sb + (wn * 64 + ni * 16) * LDS_PAD + ks * 8, LDS_PAD);
            #pragma unroll
            for (int mi = 0; mi < 2; mi++)
                #pragma unroll
                for (int i = 0; i < a[mi].num_elements; i++) {
                    float h = tf32r(a[mi].x[i]);
                    ah[mi].x[i] = h;
                    a[mi].x[i] = tf32r(a[mi].x[i] - h);
                }
            #pragma unroll
            for (int ni = 0; ni < 4; ni++)
                #pragma unroll
                for (int i = 0; i < b[ni].num_elements; i++) {
                    float h = tf32r(b[ni].x[i]);
                    bh[ni].x[i] = h;
                    b[ni].x[i] = tf32r(b[ni].x[i] - h);
                }
            #pragma unroll
            for (int mi = 0; mi < 2; mi++)
                #pragma unroll
                for (int ni = 0; ni < 4; ni++) {
                    wmma::mma_sync(acc[mi][ni], ah[mi], bh[ni], acc[mi][ni]);
                    wmma::mma_sync(acc[mi][ni], ah[mi], b[ni],  acc[mi][ni]);
                    wmma::mma_sync(acc[mi][ni], a[mi],  bh[ni], acc[mi][ni]);
                }
        }

        int nkb = kb + 3;
        if (nkb < nk) issue(nkb & 3, nkb);
        CP_COMMIT();
    }

    CP_WAIT0();
    __syncthreads();
    float* stage = tsm;
    const int SLD = 132;
    #pragma unroll
    for (int r = 0; r < 2; r++) {
        if ((wm >> 1) == r) {
            #pragma unroll
            for (int mi = 0; mi < 2; mi++)
                #pragma unroll
                for (int ni = 0; ni < 4; ni++)
                    wmma::store_matrix_sync(stage + ((wm & 1) * 32 + mi * 16) * SLD + wn * 64 + ni * 16,
                                            acc[mi][ni], SLD, wmma::mem_row_major);
        }
        __syncthreads();
        #pragma unroll
        for (int it = 0; it < 8; it++) {
            int fidx = tid + it * 256;
            int lrow = fidx >> 5;
            int c4 = (fidx & 31) * 4;
            int m = mt + r * 64 + lrow;
            int n = n0 + c4;
            if (m < segM && n < N) {
                float4 v = *(float4*)(stage + lrow * SLD + c4);
                float4 bv = *(const float4*)(bp + n);
                v.x += bv.x; v.y += bv.y; v.z += bv.z; v.w += bv.w;
                *(float4*)(C + (size_t)(rowbase + m) * N + n) = v;
            }
        }
        __syncthreads();
    }
}

// ---------------- fp32 -> fp16 conversion (vectorized) ---------------------------
__global__ void cvt16(const float* __restrict__ src, __half* __restrict__ dst, int n4)
{
    int i = blockIdx.x * blockDim.x + threadIdx.x;
    if (i < n4) {
        float4 v = *(const float4*)(src + i * 4);
        __half2 h0 = __floats2half2_rn(v.x, v.y);
        __half2 h1 = __floats2half2_rn(v.z, v.w);
        *(__half2*)(dst + i * 4)     = h0;
        *(__half2*)(dst + i * 4 + 2) = h1;
    }
}

// ---------------- fuse wo @ wv (fp16 weights out) ---------------------------------
__global__ void fuse_wo_wv(const float* __restrict__ wqkv, const float* __restrict__ bqkv,
                           const float* __restrict__ wo, const float* __restrict__ bo,
                           __half* __restrict__ wch, float* __restrict__ bc)
{
    int e = blockIdx.z, n = blockIdx.y, k = threadIdx.x;
    const float* woR = wo + ((size_t)e * DOUT + n) * DOUT;
    const float* wv  = wqkv + (size_t)e * 3 * DOUT * DOUT + 2 * DOUT * DOUT;
    const float* bv  = bqkv + (size_t)e * 3 * DOUT + 2 * DOUT;
    float s = 0.f;
    for (int j = 0; j < DOUT; j++) s = fmaf(woR[j], wv[(size_t)j * DOUT + k], s);
    wch[((size_t)e * DOUT + n) * DOUT + k] = __float2half_rn(s);
    if (k == 0) {
        float sb = bo[e * DOUT + n];
        for (int j = 0; j < DOUT; j++) sb = fmaf(woR[j], bv[j], sb);
        bc[e * DOUT + n] = sb;
    }
}

// ---------------- row LayerNorm: fp32 in, optional fp32 + fp16 out ---------------
__global__ void ln_rows(const float* __restrict__ in, float* __restrict__ out32,
                        __half* __restrict__ out16, int Ncols,
                        const float* __restrict__ g, const float* __restrict__ b,
                        int gstride, int doRelu, const int* __restrict__ rowexp, int M,
                        const int* __restrict__ Mdev)
{
    int row = blockIdx.x * 8 + (threadIdx.x >> 5);
    int Mr = Mdev ? *Mdev : M;
    if (row >= Mr) return;
    int lane = threadIdx.x & 31;
    int e = rowexp ? rowexp[row] : 0;
    const float* ip = in + (size_t)row * Ncols;
    int nw = Ncols >> 5;

    float v[12];
    float s = 0.f;
    for (int i = 0; i < nw; i++) { v[i] = ip[lane + i * 32]; s += v[i]; }
    #pragma unroll
    for (int o = 16; o; o >>= 1) s += __shfl_xor_sync(0xffffffffu, s, o);
    float mu = s / (float)Ncols;

    float sq = 0.f;
    for (int i = 0; i < nw; i++) { float d = v[i] - mu; sq += d * d; }
    #pragma unroll
    for (int o = 16; o; o >>= 1) sq += __shfl_xor_sync(0xffffffffu, sq, o);
    float inv = 1.0f / sqrtf(sq / (float)Ncols + 1e-5f);

    const float* gp = g + (long)e * gstride;
    const float* bp = b + (long)e * gstride;
    for (int i = 0; i < nw; i++) {
        int c = lane + i * 32;
        float o2 = (v[i] - mu) * inv * gp[c] + bp[c];
        if (doRelu) o2 = fmaxf(o2, 0.f);
        if (out32) out32[(size_t)row * Ncols + c] = o2;
        if (out16) out16[(size_t)row * Ncols + c] = __float2half_rn(o2);
    }
}

// ---------------- router head: provisional + ambiguity flagging -------------------
__global__ void routing_kernel(const float* __restrict__ h2, const float* __restrict__ rw3,
                               const float* __restrict__ rb3, const float* __restrict__ gumbel,
                               float* __restrict__ outRW, float* __restrict__ outIdx)
{
    int tok = blockIdx.x * 8 + (threadIdx.x >> 5);
    if (tok >= BT) return;
    int lane = threadIdx.x & 31;
    const float* h = h2 + (size_t)tok * DH2;

    float acc[NE];
    #pragma unroll
    for (int j = 0; j < NE; j++) acc[j] = 0.f;
    #pragma unroll
    for (int i = 0; i < DH2 / 32; i++) {
        int k = lane + i * 32;
        float hv = h[k];
        #pragma unroll
        for (int j = 0; j < NE; j++)
            acc[j] = fmaf(hv, rw3[j * DH2 + k], acc[j]);
    }
    #pragma unroll
    for (int j = 0; j < NE; j++)
        #pragma unroll
        for (int o = 16; o; o >>= 1)
            acc[j] += __shfl_xor_sync(0xffffffffu, acc[j], o);

    if (lane == 0) {
        float z[NE];
        float best = -1e30f, second = -1e30f; int bi = 0;
        #pragma unroll
        for (int j = 0; j < NE; j++) {
            float lg = acc[j] + rb3[j];
            z[j] = (lg + gumbel[(size_t)tok * NE + j]) / 0.07f;
            if (z[j] > best) { second = best; best = z[j]; bi = j; }
            else if (z[j] > second) second = z[j];
        }
        float ex[NE], sum = 0.f;
        #pragma unroll
        for (int j = 0; j < NE; j++) { ex[j] = expf(z[j] - best); sum += ex[j]; }
        #pragma unroll
        for (int j = 0; j < NE; j++) {
            float ys = ex[j] / sum;
            float hard = (j == bi) ? 1.f : 0.f;
            outRW[(size_t)tok * NE + j] = (hard + ys) - ys;
        }
        outIdx[tok] = (float)bi;
        g_eidx[tok] = bi;
        atomicAdd(&g_cnt[bi], 1);
        if (best - second < DELTA) {
            int p = atomicAdd(&g_nflag, 1);
            g_flag[p] = tok;
        }
    }
}

__global__ void set_nseg()
{
    if (threadIdx.x == 0) { g_nseg[0] = 0; g_nseg[1] = g_nflag; }
}

// ---------------- exact routing fix for flagged tokens ---------------------------
__global__ void routing_fix(const float* __restrict__ h2f, const float* __restrict__ rw3,
                            const float* __restrict__ rb3, const float* __restrict__ gumbel,
                            float* __restrict__ outRW, float* __restrict__ outIdx)
{
    int fi = blockIdx.x * 8 + (threadIdx.x >> 5);
    if (fi >= g_nflag) return;
    int lane = threadIdx.x & 31;
    int tok = g_flag[fi];
    const float* h = h2f + (size_t)fi * DH2;

    float acc[NE];
    #pragma unroll
    for (int j = 0; j < NE; j++) acc[j] = 0.f;
    #pragma unroll
    for (int i = 0; i < DH2 / 32; i++) {
        int k = lane + i * 32;
        float hv = h[k];
        #pragma unroll
        for (int j = 0; j < NE; j++)
            acc[j] = fmaf(hv, rw3[j * DH2 + k], acc[j]);
    }
    #pragma unroll
    for (int j = 0; j < NE; j++)
        #pragma unroll
        for (int o = 16; o; o >>= 1)
            acc[j] += __shfl_xor_sync(0xffffffffu, acc[j], o);

    if (lane == 0) {
        float z[NE];
        float best = -1e30f; int bi = 0;
        #pragma unroll
        for (int j = 0; j < NE; j++) {
            float lg = acc[j] + rb3[j];
            z[j] = (lg + gumbel[(size_t)tok * NE + j]) / 0.07f;
            if (z[j] > best) { best = z[j]; bi = j; }
        }
        float ex[NE], sum = 0.f;
        #pragma unroll
        for (int j = 0; j < NE; j++) { ex[j] = expf(z[j] - best); sum += ex[j]; }
        #pragma unroll
        for (int j = 0; j < NE; j++) {
            float ys = ex[j] / sum;
            float hard = (j == bi) ? 1.f : 0.f;
            outRW[(size_t)tok * NE + j] = (hard + ys) - ys;
        }
        outIdx[tok] = (float)bi;
        int old = g_eidx[tok];
        if (bi != old) {
            atomicSub(&g_cnt[old], 1);
            atomicAdd(&g_cnt[bi], 1);
            g_eidx[tok] = bi;
        }
    }
}

__global__ void scan_kernel()
{
    if (threadIdx.x == 0 && blockIdx.x == 0) {
        int o = 0;
        for (int e = 0; e < NE; e++) { g_off[e] = o; g_cur[e] = o; o += g_cnt[e]; }
        g_off[NE] = o;
    }
}

__global__ void fill_perm()
{
    int t = blockIdx.x * blockDim.x + threadIdx.x;
    if (t < BT) {
        int e = g_eidx[t];
        int p = atomicAdd(&g_cur[e], 1);
        g_perm[p]   = t;
        g_rowexp[p] = e;
    }
}

// ---------------- final: LN(Y + O) scattered back to token order ------------------
__global__ void final_kernel(const float* __restrict__ Y, const float* __restrict__ O,
                             const float* __restrict__ ng, const float* __restrict__ nb,
                             float* __restrict__ outMain)
{
    int r = blockIdx.x * 8 + (threadIdx.x >> 5);
    if (r >= BT) return;
    int lane = threadIdx.x & 31;
    int e = g_rowexp[r];
    int t = g_perm[r];

    float v[8];
    float s = 0.f;
    #pragma unroll
    for (int i = 0; i < 8; i++) {
        int c = lane + i * 32;
        v[i] = Y[(size_t)r * DOUT + c] + O[(size_t)r * DOUT + c];
        s += v[i];
    }
    #pragma unroll
    for (int o = 16; o; o >>= 1) s += __shfl_xor_sync(0xffffffffu, s, o);
    float mu = s / (float)DOUT;
    float sq = 0.f;
    #pragma unroll
    for (int i = 0; i < 8; i++) { float d = v[i] - mu; sq += d * d; }
    #pragma unroll
    for (int o = 16; o; o >>= 1) sq += __shfl_xor_sync(0xffffffffu, sq, o);
    float inv = 1.0f / sqrtf(sq / (float)DOUT + 1e-5f);

    const float* gp = ng + (long)e * DOUT;
    const float* bp = nb + (long)e * DOUT;
    float* op = outMain + (size_t)t * DOUT;
    #pragma unroll
    for (int i = 0; i < 8; i++) {
        int c = lane + i * 32;
        op[c] = (v[i] - mu) * inv * gp[c] + bp[c];
    }
}

// ---------------- launch ----------------------------------------------------------
extern "C" void kernel_launch(void* const* d_in, const int* in_sizes, int n_in,
                              void* d_out, int out_size)
{
    const float* x      = (const float*)d_in[0];
    const float* gumbel = (const float*)d_in[1];
    const float* rw1  = (const float*)d_in[2];
    const float* rb1  = (const float*)d_in[3];
    const float* rg1  = (const float*)d_in[4];
    const float* rbe1 = (const float*)d_in[5];
    const float* rw2  = (const float*)d_in[6];
    const float* rb2  = (const float*)d_in[7];
    const float* rg2  = (const float*)d_in[8];
    const float* rbe2 = (const float*)d_in[9];
    const float* rw3  = (const float*)d_in[10];
    const float* rb3  = (const float*)d_in[11];
    const float* ew1  = (const float*)d_in[12];
    const float* eb1  = (const float*)d_in[13];
    const float* eg1  = (const float*)d_in[14];
    const float* ebe1 = (const float*)d_in[15];
    const float* ew2  = (const float*)d_in[16];
    const float* eb2  = (const float*)d_in[17];
    const float* eg2  = (const float*)d_in[18];
    const float* ebe2 = (const float*)d_in[19];
    const float* ew3  = (const float*)d_in[20];
    const float* eb3  = (const float*)d_in[21];
    const float* eg3  = (const float*)d_in[22];
    const float* ebe3 = (const float*)d_in[23];
    const float* wqkv = (const float*)d_in[24];
    const float* bqkv = (const float*)d_in[25];
    const float* wo   = (const float*)d_in[26];
    const float* bo   = (const float*)d_in[27];
    const float* ng   = (const float*)d_in[28];
    const float* nb   = (const float*)d_in[29];

    float* outMain = (float*)d_out;
    float* outRW   = outMain + (size_t)BT * DOUT;
    float* outIdx  = outRW   + (size_t)BT * NE;

    float *bufA, *bufB, *Yb, *fA, *fB, *bc;
    __half *x16, *t16a, *t16b, *y16, *wch, *rw1h, *rw2h, *ew1h, *ew2h, *ew3h;
    int *off, *perm, *rowexp, *flag, *nseg; void *cntp, *nflagp;
    cudaGetSymbolAddress((void**)&bufA,   g_bufA);
    cudaGetSymbolAddress((void**)&bufB,   g_bufB);
    cudaGetSymbolAddress((void**)&Yb,     g_Y);
    cudaGetSymbolAddress((void**)&fA,     g_fA);
    cudaGetSymbolAddress((void**)&fB,     g_fB);
    cudaGetSymbolAddress((void**)&bc,     g_bc);
    cudaGetSymbolAddress((void**)&x16,    g_x16);
    cudaGetSymbolAddress((void**)&t16a,   g_t16a);
    cudaGetSymbolAddress((void**)&t16b,   g_t16b);
    cudaGetSymbolAddress((void**)&y16,    g_y16);
    cudaGetSymbolAddress((void**)&wch,    g_wch);
    cudaGetSymbolAddress((void**)&rw1h,   g_rw1h);
    cudaGetSymbolAddress((void**)&rw2h,   g_rw2h);
    cudaGetSymbolAddress((void**)&ew1h,   g_ew1h);
    cudaGetSymbolAddress((void**)&ew2h,   g_ew2h);
    cudaGetSymbolAddress((void**)&ew3h,   g_ew3h);
    cudaGetSymbolAddress((void**)&off,    g_off);
    cudaGetSymbolAddress((void**)&perm,   g_perm);
    cudaGetSymbolAddress((void**)&rowexp, g_rowexp);
    cudaGetSymbolAddress((void**)&flag,   g_flag);
    cudaGetSymbolAddress((void**)&nseg,   g_nseg);
    cudaGetSymbolAddress(&cntp,           g_cnt);
    cudaGetSymbolAddress(&nflagp,         g_nflag);

    cudaFuncSetAttribute((const void*)gemm_h,     cudaFuncAttributeMaxDynamicSharedMemorySize, HSMEM);
    cudaFuncSetAttribute((const void*)gemm_split, cudaFuncAttributeMaxDynamicSharedMemorySize, TSMEM);

    cudaMemsetAsync(cntp, 0, NE * sizeof(int));
    cudaMemsetAsync(nflagp, 0, sizeof(int));

    // one-time prep: fp16 conversions + fused wc
    cvt16<<<(BT * DIN / 4 + 255) / 256, 256>>>(x, x16, BT * DIN / 4);
    cvt16<<<(DH * DIN / 4 + 255) / 256, 256>>>(rw1, rw1h, DH * DIN / 4);
    cvt16<<<(DH2 * DH / 4 + 255) / 256, 256>>>(rw2, rw2h, DH2 * DH / 4);
    cvt16<<<(NE * DH * DIN / 4 + 255) / 256, 256>>>(ew1, ew1h, NE * DH * DIN / 4);
    cvt16<<<(NE * DH * DH / 4 + 255) / 256, 256>>>(ew2, ew2h, NE * DH * DH / 4);
    cvt16<<<(NE * DOUT * DH / 4 + 255) / 256, 256>>>(ew3, ew3h, NE * DOUT * DH / 4);
    fuse_wo_wv<<<dim3(1, DOUT, NE), 256>>>(wqkv, bqkv, wo, bo, wch, bc);

    // ---- router (fp16 tensor cores) ----
    gemm_h<<<dim3(BT / 128, DH / 128, 1), 256, HSMEM>>>(
        x16, nullptr, rw1h, rb1, bufA, DH, DIN, nullptr, 0, 0, BT);
    ln_rows<<<BT / 8, 256>>>(bufA, nullptr, t16a, DH, rg1, rbe1, 0, 1, nullptr, BT, nullptr);
    gemm_h<<<dim3(BT / 128, 2, 1), 256, HSMEM>>>(
        t16a, nullptr, rw2h, rb2, bufB, DH2, DH, nullptr, 0, 0, BT);
    ln_rows<<<BT / 8, 256>>>(bufB, bufB, nullptr, DH2, rg2, rbe2, 0, 1, nullptr, BT, nullptr);
    routing_kernel<<<BT / 8, 256>>>(bufB, rw3, rb3, gumbel, outRW, outIdx);
    set_nseg<<<1, 32>>>();

    // ---- exact recheck of flagged tokens (split-tf32 on RAW fp32) ----
    gemm_split<<<dim3(BT / 128, DH / 128, 1), 256, TSMEM>>>(
        x, flag, rw1, rb1, fA, DH, DIN, nseg, BT);
    ln_rows<<<BT / 8, 256>>>(fA, fA, nullptr, DH, rg1, rbe1, 0, 1, nullptr, BT, (const int*)nflagp);
    gemm_split<<<dim3(BT / 128, 2, 1), 256, TSMEM>>>(
        fA, nullptr, rw2, rb2, fB, DH2, DH, nseg, BT);
    ln_rows<<<BT / 8, 256>>>(fB, fB, nullptr, DH2, rg2, rbe2, 0, 1, nullptr, BT, (const int*)nflagp);
    routing_fix<<<BT / 8, 256>>>(fB, rw3, rb3, gumbel, outRW, outIdx);

    scan_kernel<<<1, 32>>>();
    fill_perm<<<BT / 256, 256>>>();

    // ---- experts (compacted; fp16 tensor cores) ----
    gemm_h<<<dim3(BT / 128, DH / 128, NE), 256, HSMEM>>>(
        x16, perm, ew1h, eb1, bufA, DH, DIN, off, (long)DH * DIN, DH, BT);
    ln_rows<<<BT / 8, 256>>>(bufA, nullptr, t16a, DH, eg1, ebe1, DH, 1, rowexp, BT, nullptr);

    gemm_h<<<dim3(BT / 128, DH / 128, NE), 256, HSMEM>>>(
        t16a, nullptr, ew2h, eb2, bufB, DH, DH, off, (long)DH * DH, DH, BT);
    ln_rows<<<BT / 8, 256>>>(bufB, nullptr, t16b, DH, eg2, ebe2, DH, 1, rowexp, BT, nullptr);

    gemm_h<<<dim3(BT / 128, DOUT / 128, NE), 256, HSMEM>>>(
        t16b, nullptr, ew3h, eb3, Yb, DOUT, DH, off, (long)DOUT * DH, DOUT, BT);
    ln_rows<<<BT / 8, 256>>>(Yb, Yb, y16, DOUT, eg3, ebe3, DOUT, 0, rowexp, BT, nullptr);

    // attention over length-1 seq == V; V-proj and O-proj fused into wch/bc
    gemm_h<<<dim3(BT / 128, DOUT / 128, NE), 256, HSMEM>>>(
        y16, nullptr, wch, bc, bufA, DOUT, DOUT, off, (long)DOUT * DOUT, DOUT, BT);

    final_kernel<<<BT / 8, 256>>>(Yb, bufA, ng, nb, outMain);
}

// round 8
// speedup vs baseline: 3.0522x; 1.0117x over previous
#include <cuda_runtime.h>
#include <cuda_fp16.h>
#include <mma.h>
#include <math.h>
#include <stdint.h>

using namespace nvcuda;

// Problem constants
#define BT   32768
#define DIN  768
#define DH   384
#define DH2  192
#define DOUT 256
#define NE   5
#define DELTA 0.35f

// ---- tf32 split GEMM config (recheck path) ----
#define LDS_PAD 20
#define TSTAGE_FLOATS 5120
#define TSTAGE_BYTES  20480
#define TBOFF_BYTES   10240
#define TSMEM (4 * TSTAGE_BYTES)

// ---------------- scratch (device globals) ----------------
__device__ float  g_bufB[(size_t)BT * DH2];
__device__ float  g_Y[(size_t)BT * DOUT];
__device__ float  g_fA[(size_t)BT * DH];
__device__ float  g_fB[(size_t)BT * DH2];
__device__ float  g_bc[NE * DOUT];
__device__ __half g_x16[(size_t)BT * DIN];
__device__ __half g_t16a[(size_t)BT * DH];
__device__ __half g_t16b[(size_t)BT * DH];
__device__ __half g_y16[(size_t)BT * DOUT];
__device__ __half g_wch[(size_t)NE * DOUT * DOUT];
__device__ __half g_rw1h[DH * DIN];
__device__ __half g_rw2h[DH2 * DH];
__device__ __half g_ew1h[(size_t)NE * DH * DIN];
__device__ __half g_ew2h[(size_t)NE * DH * DH];
__device__ __half g_ew3h[(size_t)NE * DOUT * DH];
__device__ int    g_eidx[BT];
__device__ int    g_perm[BT];
__device__ int    g_cnt[NE];
__device__ int    g_off[NE + 1];
__device__ int    g_cur[NE];
__device__ int    g_flag[BT];
__device__ int    g_nflag;
__device__ int    g_nseg[2];

__device__ __forceinline__ float tf32r(float x) { return wmma::__float_to_tf32(x); }

__device__ __forceinline__ uint32_t smem_u32(const void* p) {
    uint32_t a;
    asm("{ .reg .u64 t; cvta.to.shared.u64 t, %1; cvt.u32.u64 %0, t; }" : "=r"(a) : "l"(p));
    return a;
}
__device__ __forceinline__ void cpasync16(uint32_t dst, const void* src) {
    asm volatile("{ .reg .u64 g; cvta.to.global.u64 g, %1;"
                 "cp.async.ca.shared.global [%0], [g], 16; }"
                 :: "r"(dst), "l"(src) : "memory");
}
#define CP_COMMIT() asm volatile("cp.async.commit_group;" ::: "memory")
#define CP_WAIT1()  asm volatile("cp.async.wait_group 1;" ::: "memory")
#define CP_WAIT2()  asm volatile("cp.async.wait_group 2;" ::: "memory")
#define CP_WAIT0()  asm volatile("cp.async.wait_group 0;" ::: "memory")

// ============ fused fp16 GEMM + bias + LayerNorm epilogue =========================
// Block: BM=64 rows x BN=N cols (full row!), 256 threads, 3-stage cp.async.
// MODE 0: LN+ReLU -> fp16    MODE 1: LN+ReLU -> fp32
// MODE 2: LN -> fp16+fp32    MODE 3: +Y residual, LN, scatter fp32 via perm
// seg != nullptr => segmented (blockIdx.z = expert); gather maps A rows.
template<int BN, int WM, int WN, int MODE>
__global__ void __launch_bounds__(256, 1)
gemm_f(const __half* __restrict__ A, const int* __restrict__ gather,
       const __half* __restrict__ W, const float* __restrict__ bias,
       const float* __restrict__ lng, const float* __restrict__ lnb,
       float* __restrict__ out32, __half* __restrict__ out16,
       const float* __restrict__ addY, const int* __restrict__ permArr,
       int K, const int* __restrict__ seg, long wstride, int bstride,
       int lnstride, int Mtot)
{
    constexpr int CH = (64 + BN) / 64;     // 16B chunks per thread per stage
    constexpr int MF = 64 / WM / 16;
    constexpr int NF = BN / WN / 16;
    constexpr int STAGE_B = (64 + BN) * 80;
    constexpr int SLD = BN + 4;
    constexpr int NW = BN / 32;

    extern __shared__ char smraw[];

    int e = 0, rowbase = 0, segM = Mtot;
    if (seg) { e = blockIdx.z; rowbase = seg[e]; segM = seg[e + 1] - rowbase; }
    int mt = blockIdx.x * 64;
    if (mt >= segM) return;

    const __half* Wp = W + (long)e * wstride;
    const float*  bp = bias + (long)e * bstride;

    int tid  = threadIdx.x;
    int wid  = tid >> 5;
    int lane = tid & 31;
    int wm = (WM == 1) ? 0 : (wid / WN);
    int wn = (WM == 1) ? wid : (wid % WN);

    // loader: chunk 0 = A row (tid>>2); chunks 1..CH-1 = B rows
    int ra = tid >> 2;
    int c8 = (tid & 3) * 8;
    int mr = mt + ra; if (mr > segM - 1) mr = segM - 1;
    int ar = gather ? gather[rowbase + mr] : rowbase + mr;
    const __half* gp[CH];
    uint32_t so[CH];
    gp[0] = A + (size_t)ar * K + c8;
    so[0] = (uint32_t)(ra * 40 + c8) * 2;
    #pragma unroll
    for (int i = 1; i < CH; i++) {
        int rb = ra + (i - 1) * 64;
        gp[i] = Wp + (size_t)rb * K + c8;
        so[i] = (uint32_t)(5120 + (rb * 40 + c8) * 2);
    }

    uint32_t smb = smem_u32(smraw);
    int nk = K / 32;

    auto issue = [&](int stage, int kb) {
        uint32_t base = smb + (uint32_t)stage * STAGE_B;
        int k = kb * 32;
        #pragma unroll
        for (int i = 0; i < CH; i++)
            cpasync16(base + so[i], gp[i] + k);
    };

    wmma::fragment<wmma::accumulator, 16, 16, 16, float> acc[MF][NF];
    #pragma unroll
    for (int mi = 0; mi < MF; mi++)
        #pragma unroll
        for (int ni = 0; ni < NF; ni++) wmma::fill_fragment(acc[mi][ni], 0.f);

    issue(0, 0); CP_COMMIT();
    issue(1, 1); CP_COMMIT();

    for (int kb = 0; kb < nk; kb++) {
        CP_WAIT1();
        __syncthreads();
        const __half* sa = (const __half*)(smraw + (kb % 3) * STAGE_B);
        const __half* sb = sa + 2560;

        #pragma unroll
        for (int ks = 0; ks < 2; ks++) {
            wmma::fragment<wmma::matrix_a, 16, 16, 16, __half, wmma::row_major> a[MF];
            wmma::fragment<wmma::matrix_b, 16, 16, 16, __half, wmma::col_major> b[NF];
            #pragma unroll
            for (int mi = 0; mi < MF; mi++)
                wmma::load_matrix_sync(a[mi], sa + (wm * (64 / WM) + mi * 16) * 40 + ks * 16, 40);
            #pragma unroll
            for (int ni = 0; ni < NF; ni++)
                wmma::load_matrix_sync(b[ni], sb + (wn * (BN / WN) + ni * 16) * 40 + ks * 16, 40);
            #pragma unroll
            for (int mi = 0; mi < MF; mi++)
                #pragma unroll
                for (int ni = 0; ni < NF; ni++)
                    wmma::mma_sync(acc[mi][ni], a[mi], b[ni], acc[mi][ni]);
        }

        int nkb = kb + 2;
        if (nkb < nk) issue(nkb % 3, nkb);
        CP_COMMIT();
    }

    // ---- epilogue: stage full 64 x BN tile, bias + LN (+relu/residual), write ----
    CP_WAIT0();
    __syncthreads();
    float* stg = (float*)smraw;
    #pragma unroll
    for (int mi = 0; mi < MF; mi++)
        #pragma unroll
        for (int ni = 0; ni < NF; ni++)
            wmma::store_matrix_sync(stg + (wm * (64 / WM) + mi * 16) * SLD + wn * (BN / WN) + ni * 16,
                                    acc[mi][ni], SLD, wmma::mem_row_major);
    __syncthreads();

    const float* gpp = lng + (long)e * lnstride;
    const float* bpp = lnb + (long)e * lnstride;

    #pragma unroll
    for (int j = 0; j < 8; j++) {
        int r = wid * 8 + j;
        int m = mt + r;
        if (m >= segM) continue;   // r uniform per warp: no shuffle divergence
        const float* srow = stg + r * SLD;

        float v[NW];
        float s = 0.f;
        #pragma unroll
        for (int i = 0; i < NW; i++) {
            int c = lane + i * 32;
            float val = srow[c] + bp[c];
            if (MODE == 3) val += addY[(size_t)(rowbase + m) * BN + c];
            v[i] = val; s += val;
        }
        #pragma unroll
        for (int o = 16; o; o >>= 1) s += __shfl_xor_sync(0xffffffffu, s, o);
        float mu = s / (float)BN;
        float sq = 0.f;
        #pragma unroll
        for (int i = 0; i < NW; i++) { float d = v[i] - mu; sq += d * d; }
        #pragma unroll
        for (int o = 16; o; o >>= 1) sq += __shfl_xor_sync(0xffffffffu, sq, o);
        float inv = 1.0f / sqrtf(sq / (float)BN + 1e-5f);

        size_t orow = (MODE == 3) ? (size_t)permArr[rowbase + m] : (size_t)(rowbase + m);
        #pragma unroll
        for (int i = 0; i < NW; i++) {
            int c = lane + i * 32;
            float o2 = (v[i] - mu) * inv * gpp[c] + bpp[c];
            if (MODE <= 1) o2 = fmaxf(o2, 0.f);
            if (MODE != 0) out32[orow * BN + c] = o2;
            if (MODE == 0 || MODE == 2) out16[orow * BN + c] = __float2half_rn(o2);
        }
    }
}

// ============ split-tf32 GEMM (~2^-24) — exact recheck path only ==================
__global__ void __launch_bounds__(256, 1)
gemm_split(const float* __restrict__ A, const int* __restrict__ gather,
           const float* __restrict__ W, const float* __restrict__ bias,
           float* __restrict__ C, int N, int K,
           const int* __restrict__ seg, int Mtot)
{
    extern __shared__ float tsm[];

    int rowbase = 0, segM = Mtot;
    if (seg) { rowbase = seg[0]; segM = seg[1] - rowbase; }
    int mt = blockIdx.x * 128;
    if (mt >= segM) return;

    const float* bp = bias;
    int n0 = blockIdx.y * 128;

    int tid = threadIdx.x;
    int wid = tid >> 5;
    int wm  = wid >> 1;
    int wn  = wid & 1;

    int rA0 = tid >> 2,         cA0 = (tid & 3) * 4;
    int rA1 = (tid + 256) >> 2;
    int mr0 = mt + rA0; if (mr0 > segM - 1) mr0 = segM - 1;
    int mr1 = mt + rA1; if (mr1 > segM - 1) mr1 = segM - 1;
    int ar0 = gather ? gather[rowbase + mr0] : rowbase + mr0;
    int ar1 = gather ? gather[rowbase + mr1] : rowbase + mr1;
    const float* ap0 = A + (size_t)ar0 * K + cA0;
    const float* ap1 = A + (size_t)ar1 * K + cA0;
    int nr0 = n0 + rA0; if (nr0 > N - 1) nr0 = N - 1;
    int nr1 = n0 + rA1; if (nr1 > N - 1) nr1 = N - 1;
    const float* bpt0 = W + (size_t)nr0 * K + cA0;
    const float* bpt1 = W + (size_t)nr1 * K + cA0;

    uint32_t smb = smem_u32(tsm);
    uint32_t offA0 = (uint32_t)(rA0 * LDS_PAD + cA0) * 4;
    uint32_t offA1 = (uint32_t)(rA1 * LDS_PAD + cA0) * 4;

    int nk = K / 16;

    auto issue = [&](int stage, int kb) {
        int k = kb * 16;
        uint32_t base = smb + stage * TSTAGE_BYTES;
        cpasync16(base + offA0, ap0 + k);
        cpasync16(base + offA1, ap1 + k);
        cpasync16(base + TBOFF_BYTES + offA0, bpt0 + k);
        cpasync16(base + TBOFF_BYTES + offA1, bpt1 + k);
    };

    wmma::fragment<wmma::accumulator, 16, 16, 8, float> acc[2][4];
    #pragma unroll
    for (int mi = 0; mi < 2; mi++)
        #pragma unroll
        for (int ni = 0; ni < 4; ni++) wmma::fill_fragment(acc[mi][ni], 0.f);

    issue(0, 0); CP_COMMIT();
    issue(1, 1); CP_COMMIT();
    issue(2, 2); CP_COMMIT();

    for (int kb = 0; kb < nk; kb++) {
        CP_WAIT2();
        __syncthreads();
        int st = kb & 3;
        const float* sa = tsm + st * TSTAGE_FLOATS;
        const float* sb = sa + 2560;

        #pragma unroll
        for (int ks = 0; ks < 2; ks++) {
            wmma::fragment<wmma::matrix_a, 16, 16, 8, wmma::precision::tf32, wmma::row_major> a[2], ah[2];
            wmma::fragment<wmma::matrix_b, 16, 16, 8, wmma::precision::tf32, wmma::col_major> b[4], bh[4];
            #pragma unroll
            for (int mi = 0; mi < 2; mi++)
                wmma::load_matrix_sync(a[mi], sa + (wm * 32 + mi * 16) * LDS_PAD + ks * 8, LDS_PAD);
            #pragma unroll
            for (int ni = 0; ni < 4; ni++)
                wmma::load_matrix_sync(b[ni], sb + (wn * 64 + ni * 16) * LDS_PAD + ks * 8, LDS_PAD);
            #pragma unroll
            for (int mi = 0; mi < 2; mi++)
                #pragma unroll
                for (int i = 0; i < a[mi].num_elements; i++) {
                    float h = tf32r(a[mi].x[i]);
                    ah[mi].x[i] = h;
                    a[mi].x[i] = tf32r(a[mi].x[i] - h);
                }
            #pragma unroll
            for (int ni = 0; ni < 4; ni++)
                #pragma unroll
                for (int i = 0; i < b[ni].num_elements; i++) {
                    float h = tf32r(b[ni].x[i]);
                    bh[ni].x[i] = h;
                    b[ni].x[i] = tf32r(b[ni].x[i] - h);
                }
            #pragma unroll
            for (int mi = 0; mi < 2; mi++)
                #pragma unroll
                for (int ni = 0; ni < 4; ni++) {
                    wmma::mma_sync(acc[mi][ni], ah[mi], bh[ni], acc[mi][ni]);
                    wmma::mma_sync(acc[mi][ni], ah[mi], b[ni],  acc[mi][ni]);
                    wmma::mma_sync(acc[mi][ni], a[mi],  bh[ni], acc[mi][ni]);
                }
        }

        int nkb = kb + 3;
        if (nkb < nk) issue(nkb & 3, nkb);
        CP_COMMIT();
    }

    CP_WAIT0();
    __syncthreads();
    float* stage = tsm;
    const int SLD = 132;
    #pragma unroll
    for (int r = 0; r < 2; r++) {
        if ((wm >> 1) == r) {
            #pragma unroll
            for (int mi = 0; mi < 2; mi++)
                #pragma unroll
                for (int ni = 0; ni < 4; ni++)
                    wmma::store_matrix_sync(stage + ((wm & 1) * 32 + mi * 16) * SLD + wn * 64 + ni * 16,
                                            acc[mi][ni], SLD, wmma::mem_row_major);
        }
        __syncthreads();
        #pragma unroll
        for (int it = 0; it < 8; it++) {
            int fidx = tid + it * 256;
            int lrow = fidx >> 5;
            int c4 = (fidx & 31) * 4;
            int m = mt + r * 64 + lrow;
            int n = n0 + c4;
            if (m < segM && n < N) {
                float4 v = *(float4*)(stage + lrow * SLD + c4);
                float4 bv = *(const float4*)(bp + n);
                v.x += bv.x; v.y += bv.y; v.z += bv.z; v.w += bv.w;
                *(float4*)(C + (size_t)(rowbase + m) * N + n) = v;
            }
        }
        __syncthreads();
    }
}

// ---------------- fp32 -> fp16 conversion (vectorized) ---------------------------
__global__ void cvt16(const float* __restrict__ src, __half* __restrict__ dst, int n4)
{
    int i = blockIdx.x * blockDim.x + threadIdx.x;
    if (i < n4) {
        float4 v = *(const float4*)(src + i * 4);
        *(__half2*)(dst + i * 4)     = __floats2half2_rn(v.x, v.y);
        *(__half2*)(dst + i * 4 + 2) = __floats2half2_rn(v.z, v.w);
    }
}

// ---------------- fuse wo @ wv (fp16 weights out) ---------------------------------
__global__ void fuse_wo_wv(const float* __restrict__ wqkv, const float* __restrict__ bqkv,
                           const float* __restrict__ wo, const float* __restrict__ bo,
                           __half* __restrict__ wch, float* __restrict__ bc)
{
    int e = blockIdx.z, n = blockIdx.y, k = threadIdx.x;
    const float* woR = wo + ((size_t)e * DOUT + n) * DOUT;
    const float* wv  = wqkv + (size_t)e * 3 * DOUT * DOUT + 2 * DOUT * DOUT;
    const float* bv  = bqkv + (size_t)e * 3 * DOUT + 2 * DOUT;
    float s = 0.f;
    for (int j = 0; j < DOUT; j++) s = fmaf(woR[j], wv[(size_t)j * DOUT + k], s);
    wch[((size_t)e * DOUT + n) * DOUT + k] = __float2half_rn(s);
    if (k == 0) {
        float sb = bo[e * DOUT + n];
        for (int j = 0; j < DOUT; j++) sb = fmaf(woR[j], bv[j], sb);
        bc[e * DOUT + n] = sb;
    }
}

// ---------------- row LayerNorm + ReLU, fp32 (recheck path only) -----------------
__global__ void ln_rows(const float* __restrict__ in, float* __restrict__ out, int Ncols,
                        const float* __restrict__ g, const float* __restrict__ b,
                        const int* __restrict__ Mdev)
{
    int row = blockIdx.x * 8 + (threadIdx.x >> 5);
    if (row >= *Mdev) return;
    int lane = threadIdx.x & 31;
    const float* ip = in + (size_t)row * Ncols;
    int nw = Ncols >> 5;

    float v[12];
    float s = 0.f;
    for (int i = 0; i < nw; i++) { v[i] = ip[lane + i * 32]; s += v[i]; }
    #pragma unroll
    for (int o = 16; o; o >>= 1) s += __shfl_xor_sync(0xffffffffu, s, o);
    float mu = s / (float)Ncols;
    float sq = 0.f;
    for (int i = 0; i < nw; i++) { float d = v[i] - mu; sq += d * d; }
    #pragma unroll
    for (int o = 16; o; o >>= 1) sq += __shfl_xor_sync(0xffffffffu, sq, o);
    float inv = 1.0f / sqrtf(sq / (float)Ncols + 1e-5f);

    float* op = out + (size_t)row * Ncols;
    for (int i = 0; i < nw; i++) {
        int c = lane + i * 32;
        op[c] = fmaxf((v[i] - mu) * inv * g[c] + b[c], 0.f);
    }
}

// ---------------- router head: provisional + ambiguity flagging -------------------
__global__ void routing_kernel(const float* __restrict__ h2, const float* __restrict__ rw3,
                               const float* __restrict__ rb3, const float* __restrict__ gumbel,
                               float* __restrict__ outRW, float* __restrict__ outIdx)
{
    int tok = blockIdx.x * 8 + (threadIdx.x >> 5);
    if (tok >= BT) return;
    int lane = threadIdx.x & 31;
    const float* h = h2 + (size_t)tok * DH2;

    float acc[NE];
    #pragma unroll
    for (int j = 0; j < NE; j++) acc[j] = 0.f;
    #pragma unroll
    for (int i = 0; i < DH2 / 32; i++) {
        int k = lane + i * 32;
        float hv = h[k];
        #pragma unroll
        for (int j = 0; j < NE; j++)
            acc[j] = fmaf(hv, rw3[j * DH2 + k], acc[j]);
    }
    #pragma unroll
    for (int j = 0; j < NE; j++)
        #pragma unroll
        for (int o = 16; o; o >>= 1)
            acc[j] += __shfl_xor_sync(0xffffffffu, acc[j], o);

    if (lane == 0) {
        float z[NE];
        float best = -1e30f, second = -1e30f; int bi = 0;
        #pragma unroll
        for (int j = 0; j < NE; j++) {
            float lg = acc[j] + rb3[j];
            z[j] = (lg + gumbel[(size_t)tok * NE + j]) / 0.07f;
            if (z[j] > best) { second = best; best = z[j]; bi = j; }
            else if (z[j] > second) second = z[j];
        }
        float ex[NE], sum = 0.f;
        #pragma unroll
        for (int j = 0; j < NE; j++) { ex[j] = expf(z[j] - best); sum += ex[j]; }
        #pragma unroll
        for (int j = 0; j < NE; j++) {
            float ys = ex[j] / sum;
            float hard = (j == bi) ? 1.f : 0.f;
            outRW[(size_t)tok * NE + j] = (hard + ys) - ys;
        }
        outIdx[tok] = (float)bi;
        g_eidx[tok] = bi;
        atomicAdd(&g_cnt[bi], 1);
        if (best - second < DELTA) {
            int p = atomicAdd(&g_nflag, 1);
            g_flag[p] = tok;
        }
    }
}

__global__ void set_nseg()
{
    if (threadIdx.x == 0) { g_nseg[0] = 0; g_nseg[1] = g_nflag; }
}

// ---------------- exact routing fix for flagged tokens ---------------------------
__global__ void routing_fix(const float* __restrict__ h2f, const float* __restrict__ rw3,
                            const float* __restrict__ rb3, const float* __restrict__ gumbel,
                            float* __restrict__ outRW, float* __restrict__ outIdx)
{
    int fi = blockIdx.x * 8 + (threadIdx.x >> 5);
    if (fi >= g_nflag) return;
    int lane = threadIdx.x & 31;
    int tok = g_flag[fi];
    const float* h = h2f + (size_t)fi * DH2;

    float acc[NE];
    #pragma unroll
    for (int j = 0; j < NE; j++) acc[j] = 0.f;
    #pragma unroll
    for (int i = 0; i < DH2 / 32; i++) {
        int k = lane + i * 32;
        float hv = h[k];
        #pragma unroll
        for (int j = 0; j < NE; j++)
            acc[j] = fmaf(hv, rw3[j * DH2 + k], acc[j]);
    }
    #pragma unroll
    for (int j = 0; j < NE; j++)
        #pragma unroll
        for (int o = 16; o; o >>= 1)
            acc[j] += __shfl_xor_sync(0xffffffffu, acc[j], o);

    if (lane == 0) {
        float z[NE];
        float best = -1e30f; int bi = 0;
        #pragma unroll
        for (int j = 0; j < NE; j++) {
            float lg = acc[j] + rb3[j];
            z[j] = (lg + gumbel[(size_t)tok * NE + j]) / 0.07f;
            if (z[j] > best) { best = z[j]; bi = j; }
        }
        float ex[NE], sum = 0.f;
        #pragma unroll
        for (int j = 0; j < NE; j++) { ex[j] = expf(z[j] - best); sum += ex[j]; }
        #pragma unroll
        for (int j = 0; j < NE; j++) {
            float ys = ex[j] / sum;
            float hard = (j == bi) ? 1.f : 0.f;
            outRW[(size_t)tok * NE + j] = (hard + ys) - ys;
        }
        outIdx[tok] = (float)bi;
        int old = g_eidx[tok];
        if (bi != old) {
            atomicSub(&g_cnt[old], 1);
            atomicAdd(&g_cnt[bi], 1);
            g_eidx[tok] = bi;
        }
    }
}

__global__ void scan_kernel()
{
    if (threadIdx.x == 0 && blockIdx.x == 0) {
        int o = 0;
        for (int e = 0; e < NE; e++) { g_off[e] = o; g_cur[e] = o; o += g_cnt[e]; }
        g_off[NE] = o;
    }
}

__global__ void fill_perm()
{
    int t = blockIdx.x * blockDim.x + threadIdx.x;
    if (t < BT) {
        int e = g_eidx[t];
        int p = atomicAdd(&g_cur[e], 1);
        g_perm[p] = t;
    }
}

// ---------------- launch ----------------------------------------------------------
#define SM384 107520   // max(3*(448*80)=107520, 64*388*4=99328)
#define SM256 76800    // max(3*(320*80)=76800,  64*260*4=66560)
#define SM192 61440    // max(3*(256*80)=61440,  64*196*4=50176)

extern "C" void kernel_launch(void* const* d_in, const int* in_sizes, int n_in,
                              void* d_out, int out_size)
{
    const float* x      = (const float*)d_in[0];
    const float* gumbel = (const float*)d_in[1];
    const float* rw1  = (const float*)d_in[2];
    const float* rb1  = (const float*)d_in[3];
    const float* rg1  = (const float*)d_in[4];
    const float* rbe1 = (const float*)d_in[5];
    const float* rw2  = (const float*)d_in[6];
    const float* rb2  = (const float*)d_in[7];
    const float* rg2  = (const float*)d_in[8];
    const float* rbe2 = (const float*)d_in[9];
    const float* rw3  = (const float*)d_in[10];
    const float* rb3  = (const float*)d_in[11];
    const float* ew1  = (const float*)d_in[12];
    const float* eb1  = (const float*)d_in[13];
    const float* eg1  = (const float*)d_in[14];
    const float* ebe1 = (const float*)d_in[15];
    const float* ew2  = (const float*)d_in[16];
    const float* eb2  = (const float*)d_in[17];
    const float* eg2  = (const float*)d_in[18];
    const float* ebe2 = (const float*)d_in[19];
    const float* ew3  = (const float*)d_in[20];
    const float* eb3  = (const float*)d_in[21];
    const float* eg3  = (const float*)d_in[22];
    const float* ebe3 = (const float*)d_in[23];
    const float* wqkv = (const float*)d_in[24];
    const float* bqkv = (const float*)d_in[25];
    const float* wo   = (const float*)d_in[26];
    const float* bo   = (const float*)d_in[27];
    const float* ng   = (const float*)d_in[28];
    const float* nb   = (const float*)d_in[29];

    float* outMain = (float*)d_out;
    float* outRW   = outMain + (size_t)BT * DOUT;
    float* outIdx  = outRW   + (size_t)BT * NE;

    float *bufB, *Yb, *fA, *fB, *bc;
    __half *x16, *t16a, *t16b, *y16, *wch, *rw1h, *rw2h, *ew1h, *ew2h, *ew3h;
    int *off, *perm, *flag, *nseg; void *cntp, *nflagp;
    cudaGetSymbolAddress((void**)&bufB, g_bufB);
    cudaGetSymbolAddress((void**)&Yb,   g_Y);
    cudaGetSymbolAddress((void**)&fA,   g_fA);
    cudaGetSymbolAddress((void**)&fB,   g_fB);
    cudaGetSymbolAddress((void**)&bc,   g_bc);
    cudaGetSymbolAddress((void**)&x16,  g_x16);
    cudaGetSymbolAddress((void**)&t16a, g_t16a);
    cudaGetSymbolAddress((void**)&t16b, g_t16b);
    cudaGetSymbolAddress((void**)&y16,  g_y16);
    cudaGetSymbolAddress((void**)&wch,  g_wch);
    cudaGetSymbolAddress((void**)&rw1h, g_rw1h);
    cudaGetSymbolAddress((void**)&rw2h, g_rw2h);
    cudaGetSymbolAddress((void**)&ew1h, g_ew1h);
    cudaGetSymbolAddress((void**)&ew2h, g_ew2h);
    cudaGetSymbolAddress((void**)&ew3h, g_ew3h);
    cudaGetSymbolAddress((void**)&off,  g_off);
    cudaGetSymbolAddress((void**)&perm, g_perm);
    cudaGetSymbolAddress((void**)&flag, g_flag);
    cudaGetSymbolAddress((void**)&nseg, g_nseg);
    cudaGetSymbolAddress(&cntp,   g_cnt);
    cudaGetSymbolAddress(&nflagp, g_nflag);

    cudaFuncSetAttribute((const void*)gemm_f<384,1,8,0>, cudaFuncAttributeMaxDynamicSharedMemorySize, SM384);
    cudaFuncSetAttribute((const void*)gemm_f<192,2,4,1>, cudaFuncAttributeMaxDynamicSharedMemorySize, SM192);
    cudaFuncSetAttribute((const void*)gemm_f<256,2,4,2>, cudaFuncAttributeMaxDynamicSharedMemorySize, SM256);
    cudaFuncSetAttribute((const void*)gemm_f<256,2,4,3>, cudaFuncAttributeMaxDynamicSharedMemorySize, SM256);
    cudaFuncSetAttribute((const void*)gemm_split,        cudaFuncAttributeMaxDynamicSharedMemorySize, TSMEM);

    cudaMemsetAsync(cntp, 0, NE * sizeof(int));
    cudaMemsetAsync(nflagp, 0, sizeof(int));

    // one-time prep: fp16 conversions + fused wc
    cvt16<<<(BT * DIN / 4 + 255) / 256, 256>>>(x, x16, BT * DIN / 4);
    cvt16<<<(DH * DIN / 4 + 255) / 256, 256>>>(rw1, rw1h, DH * DIN / 4);
    cvt16<<<(DH2 * DH / 4 + 255) / 256, 256>>>(rw2, rw2h, DH2 * DH / 4);
    cvt16<<<(NE * DH * DIN / 4 + 255) / 256, 256>>>(ew1, ew1h, NE * DH * DIN / 4);
    cvt16<<<(NE * DH * DH / 4 + 255) / 256, 256>>>(ew2, ew2h, NE * DH * DH / 4);
    cvt16<<<(NE * DOUT * DH / 4 + 255) / 256, 256>>>(ew3, ew3h, NE * DOUT * DH / 4);
    fuse_wo_wv<<<dim3(1, DOUT, NE), 256>>>(wqkv, bqkv, wo, bo, wch, bc);

    // ---- router (fused GEMM+LN) ----
    gemm_f<384,1,8,0><<<dim3(BT/64,1,1), 256, SM384>>>(
        x16, nullptr, rw1h, rb1, rg1, rbe1, nullptr, t16a, nullptr, nullptr,
        DIN, nullptr, 0, 0, 0, BT);
    gemm_f<192,2,4,1><<<dim3(BT/64,1,1), 256, SM192>>>(
        t16a, nullptr, rw2h, rb2, rg2, rbe2, bufB, nullptr, nullptr, nullptr,
        DH, nullptr, 0, 0, 0, BT);
    routing_kernel<<<BT/8, 256>>>(bufB, rw3, rb3, gumbel, outRW, outIdx);
    set_nseg<<<1, 32>>>();

    // ---- exact recheck of flagged tokens (split-tf32 on RAW fp32) ----
    gemm_split<<<dim3(BT/128, DH/128, 1), 256, TSMEM>>>(
        x, flag, rw1, rb1, fA, DH, DIN, nseg, BT);
    ln_rows<<<BT/8, 256>>>(fA, fA, DH, rg1, rbe1, (const int*)nflagp);
    gemm_split<<<dim3(BT/128, 2, 1), 256, TSMEM>>>(
        fA, nullptr, rw2, rb2, fB, DH2, DH, nseg, BT);
    ln_rows<<<BT/8, 256>>>(fB, fB, DH2, rg2, rbe2, (const int*)nflagp);
    routing_fix<<<BT/8, 256>>>(fB, rw3, rb3, gumbel, outRW, outIdx);

    scan_kernel<<<1, 32>>>();
    fill_perm<<<BT/256, 256>>>();

    // ---- experts (compacted; fused GEMM+LN) ----
    gemm_f<384,1,8,0><<<dim3(BT/64,1,NE), 256, SM384>>>(
        x16, perm, ew1h, eb1, eg1, ebe1, nullptr, t16a, nullptr, nullptr,
        DIN, off, (long)DH * DIN, DH, DH, BT);
    gemm_f<384,1,8,0><<<dim3(BT/64,1,NE), 256, SM384>>>(
        t16a, nullptr, ew2h, eb2, eg2, ebe2, nullptr, t16b, nullptr, nullptr,
        DH, off, (long)DH * DH, DH, DH, BT);
    gemm_f<256,2,4,2><<<dim3(BT/64,1,NE), 256, SM256>>>(
        t16b, nullptr, ew3h, eb3, eg3, ebe3, Yb, y16, nullptr, nullptr,
        DH, off, (long)DOUT * DH, DOUT, DOUT, BT);
    // wc GEMM + residual + final LN + scatter (attention == V; wo@wv prefused)
    gemm_f<256,2,4,3><<<dim3(BT/64,1,NE), 256, SM256>>>(
        y16, nullptr, wch, bc, ng, nb, outMain, nullptr, Yb, perm,
        DOUT, off, (long)DOUT * DOUT, DOUT, DOUT, BT);
}